// round 11
// baseline (speedup 1.0000x reference)
#include <cuda_runtime.h>
#include <cuda_bf16.h>
#include <math.h>
#include <stdint.h>

#define NB 2
#define NS 2048
#define NE 1024
#define NH 16
#define ND 64
#define NT 32            // NS / 64 key tiles
#define NTQ 16           // NS / 128 query tiles
#define NEGV (-1e9f)
#define NEGM (-1e30f)
#define QSCALE 0.125f    // 1/sqrt(64)
#define PADW 72          // bf16 elements per smem row
#define KVBUF (64 * PADW)

// Scratch (allocation-free rule: __device__ globals)
__device__ float g_v[NB*NH*NS*ND];              // fp32 projected V (exact path)
__device__ float g_sufx[NB*NH*NS*ND];           // per-row exclusive suffix: sum_{k>s} v[k][d]
__device__ float g_vt[NB*NH*ND];                // total sum_k v[k][d]
__device__ float g_tsum[NB*NH*NT*ND];           // per-tile V sums
__device__ float g_tsuf[NB*NH*NT*ND];           // exclusive tile-level suffix
__device__ __nv_bfloat16 g_qb[NB*NH*NS*ND];     // bf16 Q (pre-scaled by 1/8)
__device__ __nv_bfloat16 g_kb[NB*NH*NS*ND];     // bf16 K
__device__ __nv_bfloat16 g_vtb[NB*NH*NS*ND];    // bf16 V transposed per 64-tile: [bh][t][d][64]
// bf16 slices: x: 0=query 1=key 2=value_hi 3=value_lo ; w: 0=Wq 1=Wk 2=Wv_hi 3=Wv_lo
__device__ __nv_bfloat16 g_xb[4u*4096*1024];
__device__ __nv_bfloat16 g_wb[4u*1024*1024];

// ---------------------------------------------------------------------------
__device__ __forceinline__ void mma16816(float* c, const uint32_t* a, const uint32_t* b) {
    asm volatile("mma.sync.aligned.m16n8k16.row.col.f32.bf16.bf16.f32 "
        "{%0,%1,%2,%3}, {%4,%5,%6,%7}, {%8,%9}, {%0,%1,%2,%3};"
        : "+f"(c[0]), "+f"(c[1]), "+f"(c[2]), "+f"(c[3])
        : "r"(a[0]), "r"(a[1]), "r"(a[2]), "r"(a[3]), "r"(b[0]), "r"(b[1]));
}
__device__ __forceinline__ uint32_t pack_bf16x2(float a, float b) {
    __nv_bfloat162 t = __floats2bfloat162_rn(a, b);
    return *(uint32_t*)&t;
}
__device__ __forceinline__ uint32_t s2u(const void* p) {
    uint32_t a;
    asm("{ .reg .u64 t; cvta.to.shared.u64 t, %1; cvt.u32.u64 %0, t; }" : "=r"(a) : "l"(p));
    return a;
}
__device__ __forceinline__ void cpa16(uint32_t d, const void* s) {
    asm volatile("cp.async.cg.shared.global [%0], [%1], 16;" :: "r"(d), "l"(s));
}
__device__ __forceinline__ void cpa4(uint32_t d, const void* s) {
    asm volatile("cp.async.ca.shared.global [%0], [%1], 4;" :: "r"(d), "l"(s));
}
#define CP_COMMIT() asm volatile("cp.async.commit_group;" ::: "memory")
#define CP_WAIT1()  asm volatile("cp.async.wait_group 1;" ::: "memory")
#define CP_WAIT0()  asm volatile("cp.async.wait_group 0;" ::: "memory")

// ---------------------------------------------------------------------------
// Kernel 0: fp32 -> bf16 (hi), optionally also residual (lo) into next slice.
// (R8 measured-best config: 6 separate launches)
// ---------------------------------------------------------------------------
__global__ void f2bf_kernel(const float4* __restrict__ src, int which, int split, int n4)
{
    int i = blockIdx.x * blockDim.x + threadIdx.x;
    if (i >= n4) return;
    __nv_bfloat16* hi = (which < 4)
        ? g_xb + (size_t)which * 4096 * 1024
        : g_wb + (size_t)(which - 4) * 1024 * 1024;
    size_t loOff = (which < 4) ? (size_t)4096 * 1024 : (size_t)1024 * 1024;

    float4 v = src[i];
    __nv_bfloat16 h0 = __float2bfloat16(v.x), h1 = __float2bfloat16(v.y);
    __nv_bfloat16 h2 = __float2bfloat16(v.z), h3 = __float2bfloat16(v.w);
    __nv_bfloat162* dh = (__nv_bfloat162*)hi;
    dh[2*i]   = __nv_bfloat162(h0, h1);
    dh[2*i+1] = __nv_bfloat162(h2, h3);
    if (split) {
        __nv_bfloat162* dl = (__nv_bfloat162*)(hi + loOff);
        dl[2*i]   = __nv_bfloat162(__float2bfloat16(v.x - __bfloat162float(h0)),
                                   __float2bfloat16(v.y - __bfloat162float(h1)));
        dl[2*i+1] = __nv_bfloat162(__float2bfloat16(v.z - __bfloat162float(h2)),
                                   __float2bfloat16(v.w - __bfloat162float(h3)));
    }
}

// ---------------------------------------------------------------------------
// Kernel 1: projections via mma.sync bf16.  2 heads per block (N=128).
// z = 0: Q -> g_qb bf16 (scaled), 1: K -> g_kb, 2: V (3-mma split) -> g_v fp32 + g_vtb bf16^T
// 8 warps = 4(m) x 2(n); warp tile 32(m) x 64(n); K-chunk 64.
// ---------------------------------------------------------------------------
__global__ __launch_bounds__(256) void proj_mma(
    const float* __restrict__ bq, const float* __restrict__ bk, const float* __restrict__ bv)
{
    extern __shared__ __align__(16) char smraw[];
    __nv_bfloat16* Xh = (__nv_bfloat16*)smraw;       // [128][PADW]
    __nv_bfloat16* Wh = Xh + 128 * PADW;             // [128][PADW] (2 heads)
    __nv_bfloat16* Xl = Wh + 128 * PADW;             // (V only)
    __nv_bfloat16* Wl = Xl + 128 * PADW;             // (V only)

    const int z = blockIdx.z;
    const int split = (z == 2);
    const __nv_bfloat16* Xg  = g_xb + (size_t)z * 4096 * 1024;
    const __nv_bfloat16* Wg  = g_wb + (size_t)z * 1024 * 1024;
    const __nv_bfloat16* XgL = g_xb + (size_t)3 * 4096 * 1024;
    const __nv_bfloat16* WgL = g_wb + (size_t)3 * 1024 * 1024;
    const float* bias = (z == 0) ? bq : (z == 1) ? bk : bv;

    const int hp = blockIdx.x;                  // head pair 0..7
    const int m0 = blockIdx.y * 128;
    const int tid = threadIdx.x;
    const int wid = tid >> 5, lane = tid & 31;
    const int warpM = wid >> 1, warpN = wid & 1;
    const int gp = lane >> 2, tig = lane & 3;

    float acc[2][8][4] = {};

    for (int c = 0; c < 16; c++) {
        const int k0 = c * 64;
        __syncthreads();
        #pragma unroll
        for (int j = 0; j < 4; j++) {
            int u = tid + j * 256;
            int r = u >> 3, cg = (u & 7) * 8;
            *(uint4*)&Xh[r * PADW + cg] = *(const uint4*)(Xg + (size_t)(m0 + r) * NE + k0 + cg);
            *(uint4*)&Wh[r * PADW + cg] = *(const uint4*)(Wg + (size_t)(hp * 128 + r) * NE + k0 + cg);
            if (split) {
                *(uint4*)&Xl[r * PADW + cg] = *(const uint4*)(XgL + (size_t)(m0 + r) * NE + k0 + cg);
                *(uint4*)&Wl[r * PADW + cg] = *(const uint4*)(WgL + (size_t)(hp * 128 + r) * NE + k0 + cg);
            }
        }
        __syncthreads();

        #pragma unroll
        for (int ks = 0; ks < 4; ks++) {
            const int kc = ks * 16 + tig * 2;
            uint32_t a[2][4], al[2][4];
            #pragma unroll
            for (int mi = 0; mi < 2; mi++) {
                const int r = warpM * 32 + mi * 16 + gp;
                a[mi][0] = *(const uint32_t*)&Xh[(r    ) * PADW + kc];
                a[mi][1] = *(const uint32_t*)&Xh[(r + 8) * PADW + kc];
                a[mi][2] = *(const uint32_t*)&Xh[(r    ) * PADW + kc + 8];
                a[mi][3] = *(const uint32_t*)&Xh[(r + 8) * PADW + kc + 8];
                if (split) {
                    al[mi][0] = *(const uint32_t*)&Xl[(r    ) * PADW + kc];
                    al[mi][1] = *(const uint32_t*)&Xl[(r + 8) * PADW + kc];
                    al[mi][2] = *(const uint32_t*)&Xl[(r    ) * PADW + kc + 8];
                    al[mi][3] = *(const uint32_t*)&Xl[(r + 8) * PADW + kc + 8];
                }
            }
            #pragma unroll
            for (int ni = 0; ni < 8; ni++) {
                const int n = warpN * 64 + ni * 8 + gp;
                uint32_t b[2], bl[2];
                b[0] = *(const uint32_t*)&Wh[n * PADW + kc];
                b[1] = *(const uint32_t*)&Wh[n * PADW + kc + 8];
                if (split) {
                    bl[0] = *(const uint32_t*)&Wl[n * PADW + kc];
                    bl[1] = *(const uint32_t*)&Wl[n * PADW + kc + 8];
                }
                #pragma unroll
                for (int mi = 0; mi < 2; mi++) {
                    mma16816(acc[mi][ni], a[mi], b);
                    if (split) {
                        mma16816(acc[mi][ni], a[mi], bl);
                        mma16816(acc[mi][ni], al[mi], b);
                    }
                }
            }
        }
    }

    const int b  = m0 >> 11;
    const int s0 = m0 & (NS - 1);
    __syncthreads();

    if (z < 2) {
        const float sc = (z == 0) ? QSCALE : 1.0f;
        __nv_bfloat16* dst = (z == 0) ? g_qb : g_kb;
        const int head = hp * 2 + warpN;
        const size_t bh = (size_t)(b * NH + head);
        #pragma unroll
        for (int mi = 0; mi < 2; mi++)
            #pragma unroll
            for (int ni = 0; ni < 8; ni++) {
                const int r = warpM * 32 + mi * 16 + gp;
                const int d = ni * 8 + tig * 2;
                const float bx = bias[head * 64 + d], by = bias[head * 64 + d + 1];
                #pragma unroll
                for (int half = 0; half < 2; half++) {
                    const int s = s0 + r + half * 8;
                    float v0 = (acc[mi][ni][2*half+0] + bx) * sc;
                    float v1 = (acc[mi][ni][2*half+1] + by) * sc;
                    *(uint32_t*)&dst[(bh * NS + s) * ND + d] = pack_bf16x2(v0, v1);
                }
            }
    } else {
        float* Vst = (float*)smraw;    // [128][131] staging
        #pragma unroll
        for (int mi = 0; mi < 2; mi++)
            #pragma unroll
            for (int ni = 0; ni < 8; ni++) {
                const int r = warpM * 32 + mi * 16 + gp;
                const int cn = warpN * 64 + ni * 8 + tig * 2;
                const float bx = bias[hp * 128 + cn], by = bias[hp * 128 + cn + 1];
                #pragma unroll
                for (int half = 0; half < 2; half++) {
                    const int rr = r + half * 8;
                    Vst[rr * 131 + cn    ] = acc[mi][ni][2*half+0] + bx;
                    Vst[rr * 131 + cn + 1] = acc[mi][ni][2*half+1] + by;
                }
            }
        __syncthreads();
        // coalesced fp32 V (2 heads)
        #pragma unroll
        for (int i = 0; i < 16; i++) {
            int u = tid + i * 256;
            int r = u >> 5, c4 = (u & 31) * 4;
            int head = hp * 2 + (c4 >> 6), d = c4 & 63;
            float4 w = make_float4(Vst[r*131+c4], Vst[r*131+c4+1], Vst[r*131+c4+2], Vst[r*131+c4+3]);
            *(float4*)&g_v[((size_t)(b * NH + head) * NS + s0 + r) * ND + d] = w;
        }
        // coalesced transposed bf16 V
        const int t0 = s0 >> 6;
        #pragma unroll
        for (int i = 0; i < 32; i++) {
            int u = tid + i * 256;
            int j = (u & 31) * 2, cc = (u >> 5) & 127, tl = u >> 12;
            int head = hp * 2 + (cc >> 6), d = cc & 63;
            uint32_t p = pack_bf16x2(Vst[(tl*64 + j)*131 + cc], Vst[(tl*64 + j + 1)*131 + cc]);
            *(uint32_t*)&g_vtb[(((size_t)(b * NH + head) * NT + t0 + tl) * ND + d) * 64 + j] = p;
        }
    }
}

// ---------------------------------------------------------------------------
// Kernels 2a/2b/2c: parallel per-row exclusive suffix sums (register-buffered).
// ---------------------------------------------------------------------------
__global__ void tile_sum_kernel()
{
    const int bh = blockIdx.x, t = blockIdx.y, d = threadIdx.x;
    const float* v = g_v + ((size_t)bh * NS + t * 64) * ND + d;
    float vals[64];
    #pragma unroll
    for (int j = 0; j < 64; j++) vals[j] = v[(size_t)j * ND];
    float a = 0.f;
    #pragma unroll
    for (int j = 0; j < 64; j++) a += vals[j];
    g_tsum[((size_t)bh * NT + t) * ND + d] = a;
}
__global__ void tile_suffix_kernel()
{
    const int bh = blockIdx.x, d = threadIdx.x;
    float vals[NT];
    #pragma unroll
    for (int t = 0; t < NT; t++) vals[t] = g_tsum[((size_t)bh * NT + t) * ND + d];
    float acc = 0.f;
    #pragma unroll
    for (int t = NT - 1; t >= 0; t--) {
        g_tsuf[((size_t)bh * NT + t) * ND + d] = acc;
        acc += vals[t];
    }
    g_vt[bh * ND + d] = acc;
}
__global__ void row_suffix_kernel()
{
    const int bh = blockIdx.x, t = blockIdx.y, d = threadIdx.x;
    const float* v = g_v + ((size_t)bh * NS + t * 64) * ND + d;
    float vals[64];
    #pragma unroll
    for (int j = 0; j < 64; j++) vals[j] = v[(size_t)j * ND];
    float acc = g_tsuf[((size_t)bh * NT + t) * ND + d];
    float* sx = g_sufx + ((size_t)bh * NS + t * 64) * ND + d;
    #pragma unroll
    for (int j = 63; j >= 0; j--) {
        sx[(size_t)j * ND] = acc;
        acc += vals[j];
    }
}

// ---------------------------------------------------------------------------
// Kernel 3: register-resident flash attention, 128-row q-tiles, 512 threads,
// 3-stage cp.async pipeline.  16 warps = 8(m) x 2(k-half).
// ---------------------------------------------------------------------------
__global__ __launch_bounds__(512, 1) void attn_mma(
    const float* __restrict__ pos_bias, float* __restrict__ out)
{
    extern __shared__ __align__(16) char smr[];
    __nv_bfloat16* Qb  = (__nv_bfloat16*)smr;        // [128][72]
    __nv_bfloat16* KV0 = Qb + 128 * PADW;            // 3 slots x (K,V), each 64*PADW
    float* posw  = (float*)(KV0 + 6 * KVBUF);        // [3][192]
    float* pm    = posw + 3 * 192;                   // [128][2]
    float* pl    = pm + 256;                         // [128][2]
    float* lse_s = pl + 256;                         // [128]
    float* Obuf  = (float*)smr;                      // overlay [128][66]

    const int tqb = NTQ - 1 - blockIdx.x;            // heavy blocks first
    const int h  = blockIdx.y;
    const int b  = blockIdx.z;
    const int bh = b * NH + h;
    const int q0 = tqb * 128;
    const int ntiles = 2 * tqb + 2;
    const int tid = threadIdx.x;
    const int wid = tid >> 5, lane = tid & 31;
    const int warpM = wid >> 1, warpN = wid & 1;
    const int gp = lane >> 2, tig = lane & 3;
    const int rbase = warpM * 16 + gp;               // 0..127

    auto prefetch = [&](int t, int s) {
        const int k0 = t * 64;
        __nv_bfloat16* Ks = KV0 + s * 2 * KVBUF;
        __nv_bfloat16* Vs = Ks + KVBUF;
        {   // 64 rows x 8 chunks = 512 units, one per thread
            int r = tid >> 3, cg = (tid & 7) * 8;
            cpa16(s2u(&Ks[r * PADW + cg]), g_kb + ((size_t)bh * NS + k0 + r) * ND + cg);
            cpa16(s2u(&Vs[r * PADW + cg]), g_vtb + (((size_t)bh * NT + t) * ND + r) * 64 + cg);
        }
        if (tid < 192) {
            int idx = q0 - k0 - 63 + tid + NS - 1;   // r-kcol in [-63,127] -> window 191
            if (idx >= 0 && idx <= 2 * NS - 2)
                cpa4(s2u(&posw[s * 192 + tid]), &pos_bias[(size_t)h * (2 * NS - 1) + idx]);
            else
                posw[s * 192 + tid] = 0.f;
        }
    };

    prefetch(0, 0); CP_COMMIT();
    prefetch(1, 1); CP_COMMIT();                     // ntiles >= 2 always

    // Q tile (128 rows) -> smem -> fragments
    #pragma unroll
    for (int j = 0; j < 2; j++) {
        int u = tid + j * 512;
        int r = u >> 3, cg = (u & 7) * 8;
        *(uint4*)&Qb[r * PADW + cg] = *(const uint4*)(g_qb + ((size_t)bh * NS + q0 + r) * ND + cg);
    }
    __syncthreads();
    uint32_t aq[4][4];
    #pragma unroll
    for (int ks = 0; ks < 4; ks++) {
        const int kc = ks * 16 + tig * 2;
        aq[ks][0] = *(const uint32_t*)&Qb[(rbase    ) * PADW + kc];
        aq[ks][1] = *(const uint32_t*)&Qb[(rbase + 8) * PADW + kc];
        aq[ks][2] = *(const uint32_t*)&Qb[(rbase    ) * PADW + kc + 8];
        aq[ks][3] = *(const uint32_t*)&Qb[(rbase + 8) * PADW + kc + 8];
    }

    float oacc[8][4] = {};
    float m0r = NEGM, l0r = 0.f, m1r = NEGM, l1r = 0.f;

    for (int t = 0; t < ntiles; t++) {
        const int k0 = t * 64;
        const int off = q0 - k0;                     // >= -64
        const bool mt = (t >= ntiles - 2);           // masking tiles
        const int s = t % 3;
        CP_WAIT1();
        __syncthreads();
        if (t + 2 < ntiles) prefetch(t + 2, (t + 2) % 3);
        CP_COMMIT();

        const __nv_bfloat16* Ks = KV0 + s * 2 * KVBUF;
        const __nv_bfloat16* Vs = Ks + KVBUF;
        const float* pw = posw + s * 192;

        // ---- S = Q.K^T over this warp's k-half ----
        float cS[4][4] = {};
        #pragma unroll
        for (int ks = 0; ks < 4; ks++) {
            const int kc = ks * 16 + tig * 2;
            uint32_t bb[4][2];
            #pragma unroll
            for (int ni = 0; ni < 4; ni++) {
                const int n = warpN * 32 + ni * 8 + gp;
                bb[ni][0] = *(const uint32_t*)&Ks[n * PADW + kc];
                bb[ni][1] = *(const uint32_t*)&Ks[n * PADW + kc + 8];
            }
            #pragma unroll
            for (int ni = 0; ni < 4; ni++) mma16816(cS[ni], aq[ks], bb[ni]);
        }

        // ---- bias + mask in registers; pack SV A-frags; lse values ----
        float e0[8], e1[8];
        uint32_t sf[2][4];
        #pragma unroll
        for (int ni = 0; ni < 4; ni++) {
            const int kcol = warpN * 32 + ni * 8 + tig * 2;
            float v00 = cS[ni][0] + pw[rbase     - kcol + 63];
            float v01 = cS[ni][1] + pw[rbase     - kcol + 62];
            float v10 = cS[ni][2] + pw[rbase + 8 - kcol + 63];
            float v11 = cS[ni][3] + pw[rbase + 8 - kcol + 62];
            float p00 = v00, p01 = v01, p10 = v10, p11 = v11;
            if (mt) {
                if (kcol     > off + rbase)     { v00 = NEGM; p00 = 0.f; }
                if (kcol + 1 > off + rbase)     { v01 = NEGM; p01 = 0.f; }
                if (kcol     > off + rbase + 8) { v10 = NEGM; p10 = 0.f; }
                if (kcol + 1 > off + rbase + 8) { v11 = NEGM; p11 = 0.f; }
            }
            e0[ni*2] = v00; e0[ni*2+1] = v01;
            e1[ni*2] = v10; e1[ni*2+1] = v11;
            const int ks2 = ni >> 1;
            if ((ni & 1) == 0) {
                sf[ks2][0] = pack_bf16x2(p00, p01);
                sf[ks2][1] = pack_bf16x2(p10, p11);
            } else {
                sf[ks2][2] = pack_bf16x2(p00, p01);
                sf[ks2][3] = pack_bf16x2(p10, p11);
            }
        }
        // ---- online lse (register-only; fully-masked tiles contribute 0) ----
        {
            float vm = e0[0];
            #pragma unroll
            for (int j = 1; j < 8; j++) vm = fmaxf(vm, e0[j]);
            float mn = fmaxf(m0r, vm);
            float sum = 0.f;
            #pragma unroll
            for (int j = 0; j < 8; j++) sum += __expf(e0[j] - mn);
            l0r = l0r * __expf(m0r - mn) + sum; m0r = mn;
        }
        {
            float vm = e1[0];
            #pragma unroll
            for (int j = 1; j < 8; j++) vm = fmaxf(vm, e1[j]);
            float mn = fmaxf(m1r, vm);
            float sum = 0.f;
            #pragma unroll
            for (int j = 0; j < 8; j++) sum += __expf(e1[j] - mn);
            l1r = l1r * __expf(m1r - mn) + sum; m1r = mn;
        }

        // ---- O += S.V over this warp's k-half (full 64 d) ----
        #pragma unroll
        for (int ks2 = 0; ks2 < 2; ks2++) {
            const int kc = warpN * 32 + ks2 * 16 + tig * 2;
            #pragma unroll
            for (int ni = 0; ni < 8; ni++) {
                const int n = ni * 8 + gp;
                uint32_t bb[2];
                bb[0] = *(const uint32_t*)&Vs[n * PADW + kc];
                bb[1] = *(const uint32_t*)&Vs[n * PADW + kc + 8];
                mma16816(oacc[ni], sf[ks2], bb);
            }
        }
    }

    CP_WAIT0();
    __syncthreads();
    // reduce (m,l) across tig lanes
    #pragma unroll
    for (int d = 1; d < 4; d <<= 1) {
        float mo = __shfl_xor_sync(0xffffffffu, m0r, d);
        float lo = __shfl_xor_sync(0xffffffffu, l0r, d);
        float mn = fmaxf(m0r, mo);
        l0r = l0r * __expf(m0r - mn) + lo * __expf(mo - mn); m0r = mn;
        mo = __shfl_xor_sync(0xffffffffu, m1r, d);
        lo = __shfl_xor_sync(0xffffffffu, l1r, d);
        mn = fmaxf(m1r, mo);
        l1r = l1r * __expf(m1r - mn) + lo * __expf(mo - mn); m1r = mn;
    }
    if (tig == 0) {
        pm[rbase * 2 + warpN] = m0r;       pl[rbase * 2 + warpN] = l0r;
        pm[(rbase + 8) * 2 + warpN] = m1r; pl[(rbase + 8) * 2 + warpN] = l1r;
    }
    __syncthreads();
    if (tid < 128) {
        float ma = pm[tid*2], mb_ = pm[tid*2+1], la = pl[tid*2], lb = pl[tid*2+1];
        float mn = fmaxf(ma, mb_);
        lse_s[tid] = mn + logf(la * __expf(ma - mn) + lb * __expf(mb_ - mn));
    }
    __syncthreads();
    // cross-warpN O combine
    if (warpN == 1) {
        #pragma unroll
        for (int ni = 0; ni < 8; ni++) {
            const int d = ni * 8 + tig * 2;
            Obuf[rbase * 66 + d]           = oacc[ni][0];
            Obuf[rbase * 66 + d + 1]       = oacc[ni][1];
            Obuf[(rbase + 8) * 66 + d]     = oacc[ni][2];
            Obuf[(rbase + 8) * 66 + d + 1] = oacc[ni][3];
        }
    }
    __syncthreads();
    if (warpN == 0) {
        const float lse0 = lse_s[rbase], lse1 = lse_s[rbase + 8];
        const int q0r = q0 + rbase;
        #pragma unroll
        for (int ni = 0; ni < 8; ni++) {
            const int d = ni * 8 + tig * 2;
            float2 vt2 = *(const float2*)&g_vt[bh * ND + d];
            float2 sx0 = *(const float2*)&g_sufx[((size_t)bh * NS + q0r    ) * ND + d];
            float2 sx1 = *(const float2*)&g_sufx[((size_t)bh * NS + q0r + 8) * ND + d];
            float2 o0, o1;
            o0.x = oacc[ni][0] + Obuf[rbase * 66 + d]     + NEGV * sx0.x - lse0 * vt2.x;
            o0.y = oacc[ni][1] + Obuf[rbase * 66 + d + 1] + NEGV * sx0.y - lse0 * vt2.y;
            o1.x = oacc[ni][2] + Obuf[(rbase+8) * 66 + d]     + NEGV * sx1.x - lse1 * vt2.x;
            o1.y = oacc[ni][3] + Obuf[(rbase+8) * 66 + d + 1] + NEGV * sx1.y - lse1 * vt2.y;
            *(float2*)&out[(((size_t)b * NS + q0r    ) * NH + h) * ND + d] = o0;
            *(float2*)&out[(((size_t)b * NS + q0r + 8) * NH + h) * ND + d] = o1;
        }
    }
}

// ---------------------------------------------------------------------------
extern "C" void kernel_launch(void* const* d_in, const int* in_sizes, int n_in,
                              void* d_out, int out_size)
{
    (void)in_sizes; (void)n_in; (void)out_size;
    const float* query = (const float*)d_in[0];
    const float* key_  = (const float*)d_in[1];
    const float* value = (const float*)d_in[2];
    const float* Wq    = (const float*)d_in[3];
    const float* bq    = (const float*)d_in[4];
    const float* Wk    = (const float*)d_in[5];
    const float* bk    = (const float*)d_in[6];
    const float* Wv    = (const float*)d_in[7];
    const float* bv    = (const float*)d_in[8];
    const float* pos   = (const float*)d_in[9];

    const int n4x = 4096 * 1024 / 4, n4w = 1024 * 1024 / 4;
    f2bf_kernel<<<n4x / 256, 256>>>((const float4*)query, 0, 0, n4x);
    f2bf_kernel<<<n4x / 256, 256>>>((const float4*)key_,  1, 0, n4x);
    f2bf_kernel<<<n4x / 256, 256>>>((const float4*)value, 2, 1, n4x);
    f2bf_kernel<<<n4w / 256, 256>>>((const float4*)Wq,    4, 0, n4w);
    f2bf_kernel<<<n4w / 256, 256>>>((const float4*)Wk,    5, 0, n4w);
    f2bf_kernel<<<n4w / 256, 256>>>((const float4*)Wv,    6, 1, n4w);

    const int PROJ_SMEM = 4 * 128 * PADW * 2;   // 73728 B (>= 128*131*4 staging)
    cudaFuncSetAttribute(proj_mma, cudaFuncAttributeMaxDynamicSharedMemorySize, PROJ_SMEM);
    proj_mma<<<dim3(8, 32, 3), 256, PROJ_SMEM>>>(bq, bk, bv);

    tile_sum_kernel<<<dim3(NB * NH, NT), 64>>>();
    tile_suffix_kernel<<<dim3(NB * NH), 64>>>();
    row_suffix_kernel<<<dim3(NB * NH, NT), 64>>>();

    // Qb[128] + 3*(K,V) + posw[3][192] + pm/pl[128][2] + lse[128]
    const int ATTN_SMEM = 128*PADW*2 + 6*KVBUF*2 + (3*192 + 256 + 256 + 128) * 4;  // 78592 B
    cudaFuncSetAttribute(attn_mma, cudaFuncAttributeMaxDynamicSharedMemorySize, ATTN_SMEM);
    attn_mma<<<dim3(NTQ, NH, NB), 512, ATTN_SMEM>>>(pos, (float*)d_out);
}

// round 12
// speedup vs baseline: 1.0095x; 1.0095x over previous
#include <cuda_runtime.h>
#include <cuda_bf16.h>
#include <math.h>
#include <stdint.h>

#define NB 2
#define NS 2048
#define NE 1024
#define NH 16
#define ND 64
#define NT 32            // NS / 64 key tiles
#define NEGV (-1e9f)
#define NEGM (-1e30f)
#define QSCALE 0.125f    // 1/sqrt(64)
#define PADW 72          // bf16 elements per smem row
#define KVBUF (64 * PADW)

// Scratch (allocation-free rule: __device__ globals)
__device__ float g_v[NB*NH*NS*ND];              // fp32 projected V (exact path)
__device__ float g_sufx[NB*NH*NS*ND];           // per-row exclusive suffix: sum_{k>s} v[k][d]
__device__ float g_vt[NB*NH*ND];                // total sum_k v[k][d]
__device__ float g_tsum[NB*NH*NT*ND];           // per-tile V sums
__device__ float g_tsuf[NB*NH*NT*ND];           // exclusive tile-level suffix
__device__ __nv_bfloat16 g_qb[NB*NH*NS*ND];     // bf16 Q (pre-scaled by 1/8)
__device__ __nv_bfloat16 g_kb[NB*NH*NS*ND];     // bf16 K
__device__ __nv_bfloat16 g_vtb[NB*NH*NS*ND];    // bf16 V transposed per 64-tile: [bh][t][d][64]
// bf16 slices: x: 0=query 1=key 2=value_hi 3=value_lo ; w: 0=Wq 1=Wk 2=Wv_hi 3=Wv_lo
__device__ __nv_bfloat16 g_xb[4u*4096*1024];
__device__ __nv_bfloat16 g_wb[4u*1024*1024];

// ---------------------------------------------------------------------------
__device__ __forceinline__ void mma16816(float* c, const uint32_t* a, const uint32_t* b) {
    asm volatile("mma.sync.aligned.m16n8k16.row.col.f32.bf16.bf16.f32 "
        "{%0,%1,%2,%3}, {%4,%5,%6,%7}, {%8,%9}, {%0,%1,%2,%3};"
        : "+f"(c[0]), "+f"(c[1]), "+f"(c[2]), "+f"(c[3])
        : "r"(a[0]), "r"(a[1]), "r"(a[2]), "r"(a[3]), "r"(b[0]), "r"(b[1]));
}
__device__ __forceinline__ uint32_t pack_bf16x2(float a, float b) {
    __nv_bfloat162 t = __floats2bfloat162_rn(a, b);
    return *(uint32_t*)&t;
}
__device__ __forceinline__ uint32_t s2u(const void* p) {
    uint32_t a;
    asm("{ .reg .u64 t; cvta.to.shared.u64 t, %1; cvt.u32.u64 %0, t; }" : "=r"(a) : "l"(p));
    return a;
}
__device__ __forceinline__ void cpa16(uint32_t d, const void* s) {
    asm volatile("cp.async.cg.shared.global [%0], [%1], 16;" :: "r"(d), "l"(s));
}
__device__ __forceinline__ void cpa4(uint32_t d, const void* s) {
    asm volatile("cp.async.ca.shared.global [%0], [%1], 4;" :: "r"(d), "l"(s));
}
#define CP_COMMIT() asm volatile("cp.async.commit_group;" ::: "memory")
#define CP_WAIT1()  asm volatile("cp.async.wait_group 1;" ::: "memory")
#define CP_WAIT0()  asm volatile("cp.async.wait_group 0;" ::: "memory")

// ---------------------------------------------------------------------------
// Kernel 0: fp32 -> bf16 (hi), optionally also residual (lo) into next slice.
// ---------------------------------------------------------------------------
__global__ void f2bf_kernel(const float4* __restrict__ src, int which, int split, int n4)
{
    int i = blockIdx.x * blockDim.x + threadIdx.x;
    if (i >= n4) return;
    __nv_bfloat16* hi = (which < 4)
        ? g_xb + (size_t)which * 4096 * 1024
        : g_wb + (size_t)(which - 4) * 1024 * 1024;
    size_t loOff = (which < 4) ? (size_t)4096 * 1024 : (size_t)1024 * 1024;

    float4 v = src[i];
    __nv_bfloat16 h0 = __float2bfloat16(v.x), h1 = __float2bfloat16(v.y);
    __nv_bfloat16 h2 = __float2bfloat16(v.z), h3 = __float2bfloat16(v.w);
    __nv_bfloat162* dh = (__nv_bfloat162*)hi;
    dh[2*i]   = __nv_bfloat162(h0, h1);
    dh[2*i+1] = __nv_bfloat162(h2, h3);
    if (split) {
        __nv_bfloat162* dl = (__nv_bfloat162*)(hi + loOff);
        dl[2*i]   = __nv_bfloat162(__float2bfloat16(v.x - __bfloat162float(h0)),
                                   __float2bfloat16(v.y - __bfloat162float(h1)));
        dl[2*i+1] = __nv_bfloat162(__float2bfloat16(v.z - __bfloat162float(h2)),
                                   __float2bfloat16(v.w - __bfloat162float(h3)));
    }
}

// ---------------------------------------------------------------------------
// Kernel 1: projections via mma.sync bf16.  2 heads per block (N=128).
// z = 0: Q -> g_qb bf16 (scaled), 1: K -> g_kb, 2: V (3-mma split) -> g_v fp32 + g_vtb bf16^T
// 8 warps = 4(m) x 2(n); warp tile 32(m) x 64(n); K-chunk 64.
// ---------------------------------------------------------------------------
__global__ __launch_bounds__(256) void proj_mma(
    const float* __restrict__ bq, const float* __restrict__ bk, const float* __restrict__ bv)
{
    extern __shared__ __align__(16) char smraw[];
    __nv_bfloat16* Xh = (__nv_bfloat16*)smraw;       // [128][PADW]
    __nv_bfloat16* Wh = Xh + 128 * PADW;             // [128][PADW] (2 heads)
    __nv_bfloat16* Xl = Wh + 128 * PADW;             // (V only)
    __nv_bfloat16* Wl = Xl + 128 * PADW;             // (V only)

    const int z = blockIdx.z;
    const int split = (z == 2);
    const __nv_bfloat16* Xg  = g_xb + (size_t)z * 4096 * 1024;
    const __nv_bfloat16* Wg  = g_wb + (size_t)z * 1024 * 1024;
    const __nv_bfloat16* XgL = g_xb + (size_t)3 * 4096 * 1024;
    const __nv_bfloat16* WgL = g_wb + (size_t)3 * 1024 * 1024;
    const float* bias = (z == 0) ? bq : (z == 1) ? bk : bv;

    const int hp = blockIdx.x;                  // head pair 0..7
    const int m0 = blockIdx.y * 128;
    const int tid = threadIdx.x;
    const int wid = tid >> 5, lane = tid & 31;
    const int warpM = wid >> 1, warpN = wid & 1;
    const int gp = lane >> 2, tig = lane & 3;

    float acc[2][8][4] = {};

    for (int c = 0; c < 16; c++) {
        const int k0 = c * 64;
        __syncthreads();
        #pragma unroll
        for (int j = 0; j < 4; j++) {
            int u = tid + j * 256;
            int r = u >> 3, cg = (u & 7) * 8;
            *(uint4*)&Xh[r * PADW + cg] = *(const uint4*)(Xg + (size_t)(m0 + r) * NE + k0 + cg);
            *(uint4*)&Wh[r * PADW + cg] = *(const uint4*)(Wg + (size_t)(hp * 128 + r) * NE + k0 + cg);
            if (split) {
                *(uint4*)&Xl[r * PADW + cg] = *(const uint4*)(XgL + (size_t)(m0 + r) * NE + k0 + cg);
                *(uint4*)&Wl[r * PADW + cg] = *(const uint4*)(WgL + (size_t)(hp * 128 + r) * NE + k0 + cg);
            }
        }
        __syncthreads();

        #pragma unroll
        for (int ks = 0; ks < 4; ks++) {
            const int kc = ks * 16 + tig * 2;
            uint32_t a[2][4], al[2][4];
            #pragma unroll
            for (int mi = 0; mi < 2; mi++) {
                const int r = warpM * 32 + mi * 16 + gp;
                a[mi][0] = *(const uint32_t*)&Xh[(r    ) * PADW + kc];
                a[mi][1] = *(const uint32_t*)&Xh[(r + 8) * PADW + kc];
                a[mi][2] = *(const uint32_t*)&Xh[(r    ) * PADW + kc + 8];
                a[mi][3] = *(const uint32_t*)&Xh[(r + 8) * PADW + kc + 8];
                if (split) {
                    al[mi][0] = *(const uint32_t*)&Xl[(r    ) * PADW + kc];
                    al[mi][1] = *(const uint32_t*)&Xl[(r + 8) * PADW + kc];
                    al[mi][2] = *(const uint32_t*)&Xl[(r    ) * PADW + kc + 8];
                    al[mi][3] = *(const uint32_t*)&Xl[(r + 8) * PADW + kc + 8];
                }
            }
            #pragma unroll
            for (int ni = 0; ni < 8; ni++) {
                const int n = warpN * 64 + ni * 8 + gp;
                uint32_t b[2], bl[2];
                b[0] = *(const uint32_t*)&Wh[n * PADW + kc];
                b[1] = *(const uint32_t*)&Wh[n * PADW + kc + 8];
                if (split) {
                    bl[0] = *(const uint32_t*)&Wl[n * PADW + kc];
                    bl[1] = *(const uint32_t*)&Wl[n * PADW + kc + 8];
                }
                #pragma unroll
                for (int mi = 0; mi < 2; mi++) {
                    mma16816(acc[mi][ni], a[mi], b);
                    if (split) {
                        mma16816(acc[mi][ni], a[mi], bl);
                        mma16816(acc[mi][ni], al[mi], b);
                    }
                }
            }
        }
    }

    const int b  = m0 >> 11;
    const int s0 = m0 & (NS - 1);
    __syncthreads();

    if (z < 2) {
        const float sc = (z == 0) ? QSCALE : 1.0f;
        __nv_bfloat16* dst = (z == 0) ? g_qb : g_kb;
        const int head = hp * 2 + warpN;
        const size_t bh = (size_t)(b * NH + head);
        #pragma unroll
        for (int mi = 0; mi < 2; mi++)
            #pragma unroll
            for (int ni = 0; ni < 8; ni++) {
                const int r = warpM * 32 + mi * 16 + gp;
                const int d = ni * 8 + tig * 2;
                const float bx = bias[head * 64 + d], by = bias[head * 64 + d + 1];
                #pragma unroll
                for (int half = 0; half < 2; half++) {
                    const int s = s0 + r + half * 8;
                    float v0 = (acc[mi][ni][2*half+0] + bx) * sc;
                    float v1 = (acc[mi][ni][2*half+1] + by) * sc;
                    *(uint32_t*)&dst[(bh * NS + s) * ND + d] = pack_bf16x2(v0, v1);
                }
            }
    } else {
        float* Vst = (float*)smraw;    // [128][131] staging
        #pragma unroll
        for (int mi = 0; mi < 2; mi++)
            #pragma unroll
            for (int ni = 0; ni < 8; ni++) {
                const int r = warpM * 32 + mi * 16 + gp;
                const int cn = warpN * 64 + ni * 8 + tig * 2;
                const float bx = bias[hp * 128 + cn], by = bias[hp * 128 + cn + 1];
                #pragma unroll
                for (int half = 0; half < 2; half++) {
                    const int rr = r + half * 8;
                    Vst[rr * 131 + cn    ] = acc[mi][ni][2*half+0] + bx;
                    Vst[rr * 131 + cn + 1] = acc[mi][ni][2*half+1] + by;
                }
            }
        __syncthreads();
        // coalesced fp32 V (2 heads)
        #pragma unroll
        for (int i = 0; i < 16; i++) {
            int u = tid + i * 256;
            int r = u >> 5, c4 = (u & 31) * 4;
            int head = hp * 2 + (c4 >> 6), d = c4 & 63;
            float4 w = make_float4(Vst[r*131+c4], Vst[r*131+c4+1], Vst[r*131+c4+2], Vst[r*131+c4+3]);
            *(float4*)&g_v[((size_t)(b * NH + head) * NS + s0 + r) * ND + d] = w;
        }
        // coalesced transposed bf16 V
        const int t0 = s0 >> 6;
        #pragma unroll
        for (int i = 0; i < 32; i++) {
            int u = tid + i * 256;
            int j = (u & 31) * 2, cc = (u >> 5) & 127, tl = u >> 12;
            int head = hp * 2 + (cc >> 6), d = cc & 63;
            uint32_t p = pack_bf16x2(Vst[(tl*64 + j)*131 + cc], Vst[(tl*64 + j + 1)*131 + cc]);
            *(uint32_t*)&g_vtb[(((size_t)(b * NH + head) * NT + t0 + tl) * ND + d) * 64 + j] = p;
        }
    }
}

// ---------------------------------------------------------------------------
// Kernels 2a/2b/2c: parallel per-row exclusive suffix sums (register-buffered).
// ---------------------------------------------------------------------------
__global__ void tile_sum_kernel()
{
    const int bh = blockIdx.x, t = blockIdx.y, d = threadIdx.x;
    const float* v = g_v + ((size_t)bh * NS + t * 64) * ND + d;
    float vals[64];
    #pragma unroll
    for (int j = 0; j < 64; j++) vals[j] = v[(size_t)j * ND];
    float a = 0.f;
    #pragma unroll
    for (int j = 0; j < 64; j++) a += vals[j];
    g_tsum[((size_t)bh * NT + t) * ND + d] = a;
}
__global__ void tile_suffix_kernel()
{
    const int bh = blockIdx.x, d = threadIdx.x;
    float vals[NT];
    #pragma unroll
    for (int t = 0; t < NT; t++) vals[t] = g_tsum[((size_t)bh * NT + t) * ND + d];
    float acc = 0.f;
    #pragma unroll
    for (int t = NT - 1; t >= 0; t--) {
        g_tsuf[((size_t)bh * NT + t) * ND + d] = acc;
        acc += vals[t];
    }
    g_vt[bh * ND + d] = acc;
}
__global__ void row_suffix_kernel()
{
    const int bh = blockIdx.x, t = blockIdx.y, d = threadIdx.x;
    const float* v = g_v + ((size_t)bh * NS + t * 64) * ND + d;
    float vals[64];
    #pragma unroll
    for (int j = 0; j < 64; j++) vals[j] = v[(size_t)j * ND];
    float acc = g_tsuf[((size_t)bh * NT + t) * ND + d];
    float* sx = g_sufx + ((size_t)bh * NS + t * 64) * ND + d;
    #pragma unroll
    for (int j = 63; j >= 0; j--) {
        sx[(size_t)j * ND] = acc;
        acc += vals[j];
    }
}

// ---------------------------------------------------------------------------
// Kernel 3: register-resident flash attention, 3-stage cp.async pipeline.
// (R8 measured-best: 64-row q-tiles, 256 threads, occ 2, tail-first)
// ---------------------------------------------------------------------------
__global__ __launch_bounds__(256, 2) void attn_mma(
    const float* __restrict__ pos_bias, float* __restrict__ out)
{
    extern __shared__ __align__(16) char smr[];
    __nv_bfloat16* Qb  = (__nv_bfloat16*)smr;        // [64][72]
    __nv_bfloat16* KV0 = Qb + 64 * PADW;             // 3 slots x (K,V), each 64*PADW
    float* posw  = (float*)(KV0 + 6 * KVBUF);        // [3][128]
    float* pm    = posw + 384;                       // [64][2]
    float* pl    = pm + 128;                         // [64][2]
    float* lse_s = pl + 128;                         // [64]
    float* Obuf  = (float*)smr;                      // overlay [64][66]

    const int tq = NT - 1 - blockIdx.x;              // heavy blocks first
    const int h  = blockIdx.y;
    const int b  = blockIdx.z;
    const int bh = b * NH + h;
    const int q0 = tq * 64;
    const int tid = threadIdx.x;
    const int wid = tid >> 5, lane = tid & 31;
    const int warpM = wid >> 1, warpN = wid & 1;
    const int gp = lane >> 2, tig = lane & 3;
    const int rbase = warpM * 16 + gp;

    auto prefetch = [&](int t, int s) {
        const int k0 = t * 64;
        __nv_bfloat16* Ks = KV0 + s * 2 * KVBUF;
        __nv_bfloat16* Vs = Ks + KVBUF;
        #pragma unroll
        for (int j = 0; j < 2; j++) {
            int u = tid + j * 256;
            int r = u >> 3, cg = (u & 7) * 8;
            cpa16(s2u(&Ks[r * PADW + cg]), g_kb + ((size_t)bh * NS + k0 + r) * ND + cg);
            cpa16(s2u(&Vs[r * PADW + cg]), g_vtb + (((size_t)bh * NT + t) * ND + r) * 64 + cg);
        }
        if (tid < 128) {
            int idx = q0 - k0 - 63 + tid + NS - 1;
            if (idx <= 2 * NS - 2)
                cpa4(s2u(&posw[s * 128 + tid]), &pos_bias[(size_t)h * (2 * NS - 1) + idx]);
            else
                posw[s * 128 + tid] = 0.f;
        }
    };

    prefetch(0, 0); CP_COMMIT();
    if (tq >= 1) prefetch(1, 1);
    CP_COMMIT();

    // Q tile -> smem -> fragments (resident all tiles)
    #pragma unroll
    for (int j = 0; j < 2; j++) {
        int u = tid + j * 256;
        int r = u >> 3, cg = (u & 7) * 8;
        *(uint4*)&Qb[r * PADW + cg] = *(const uint4*)(g_qb + ((size_t)bh * NS + q0 + r) * ND + cg);
    }
    __syncthreads();
    uint32_t aq[4][4];
    #pragma unroll
    for (int ks = 0; ks < 4; ks++) {
        const int kc = ks * 16 + tig * 2;
        aq[ks][0] = *(const uint32_t*)&Qb[(rbase    ) * PADW + kc];
        aq[ks][1] = *(const uint32_t*)&Qb[(rbase + 8) * PADW + kc];
        aq[ks][2] = *(const uint32_t*)&Qb[(rbase    ) * PADW + kc + 8];
        aq[ks][3] = *(const uint32_t*)&Qb[(rbase + 8) * PADW + kc + 8];
    }

    float oacc[8][4] = {};
    float m0r = NEGM, l0r = 0.f, m1r = NEGM, l1r = 0.f;

    for (int t = 0; t <= tq; t++) {
        const bool diag = (t == tq);
        const int s = t % 3;
        CP_WAIT1();
        __syncthreads();
        if (t + 2 <= tq) prefetch(t + 2, (t + 2) % 3);
        CP_COMMIT();

        const __nv_bfloat16* Ks = KV0 + s * 2 * KVBUF;
        const __nv_bfloat16* Vs = Ks + KVBUF;
        const float* pw = posw + s * 128;

        // ---- S = Q.K^T over this warp's k-half ----
        float cS[4][4] = {};
        #pragma unroll
        for (int ks = 0; ks < 4; ks++) {
            const int kc = ks * 16 + tig * 2;
            uint32_t bb[4][2];
            #pragma unroll
            for (int ni = 0; ni < 4; ni++) {
                const int n = warpN * 32 + ni * 8 + gp;
                bb[ni][0] = *(const uint32_t*)&Ks[n * PADW + kc];
                bb[ni][1] = *(const uint32_t*)&Ks[n * PADW + kc + 8];
            }
            #pragma unroll
            for (int ni = 0; ni < 4; ni++) mma16816(cS[ni], aq[ks], bb[ni]);
        }

        // ---- bias + mask in registers; pack SV A-frags; lse values ----
        float e0[8], e1[8];
        uint32_t sf[2][4];
        #pragma unroll
        for (int ni = 0; ni < 4; ni++) {
            const int kcol = warpN * 32 + ni * 8 + tig * 2;
            float v00 = cS[ni][0] + pw[rbase     - kcol + 63];
            float v01 = cS[ni][1] + pw[rbase     - kcol + 62];
            float v10 = cS[ni][2] + pw[rbase + 8 - kcol + 63];
            float v11 = cS[ni][3] + pw[rbase + 8 - kcol + 62];
            float p00 = v00, p01 = v01, p10 = v10, p11 = v11;
            if (diag) {
                if (kcol     > rbase)     { v00 = NEGM; p00 = 0.f; }
                if (kcol + 1 > rbase)     { v01 = NEGM; p01 = 0.f; }
                if (kcol     > rbase + 8) { v10 = NEGM; p10 = 0.f; }
                if (kcol + 1 > rbase + 8) { v11 = NEGM; p11 = 0.f; }
            }
            e0[ni*2] = v00; e0[ni*2+1] = v01;
            e1[ni*2] = v10; e1[ni*2+1] = v11;
            const int ks2 = ni >> 1;
            if ((ni & 1) == 0) {
                sf[ks2][0] = pack_bf16x2(p00, p01);
                sf[ks2][1] = pack_bf16x2(p10, p11);
            } else {
                sf[ks2][2] = pack_bf16x2(p00, p01);
                sf[ks2][3] = pack_bf16x2(p10, p11);
            }
        }
        // ---- online lse (register-only) ----
        {
            float vm = e0[0];
            #pragma unroll
            for (int j = 1; j < 8; j++) vm = fmaxf(vm, e0[j]);
            float mn = fmaxf(m0r, vm);
            float sum = 0.f;
            #pragma unroll
            for (int j = 0; j < 8; j++) sum += __expf(e0[j] - mn);
            l0r = l0r * __expf(m0r - mn) + sum; m0r = mn;
        }
        {
            float vm = e1[0];
            #pragma unroll
            for (int j = 1; j < 8; j++) vm = fmaxf(vm, e1[j]);
            float mn = fmaxf(m1r, vm);
            float sum = 0.f;
            #pragma unroll
            for (int j = 0; j < 8; j++) sum += __expf(e1[j] - mn);
            l1r = l1r * __expf(m1r - mn) + sum; m1r = mn;
        }

        // ---- O += S.V over this warp's k-half (full 64 d) ----
        #pragma unroll
        for (int ks2 = 0; ks2 < 2; ks2++) {
            const int kc = warpN * 32 + ks2 * 16 + tig * 2;
            #pragma unroll
            for (int ni = 0; ni < 8; ni++) {
                const int n = ni * 8 + gp;
                uint32_t bb[2];
                bb[0] = *(const uint32_t*)&Vs[n * PADW + kc];
                bb[1] = *(const uint32_t*)&Vs[n * PADW + kc + 8];
                mma16816(oacc[ni], sf[ks2], bb);
            }
        }
    }

    CP_WAIT0();
    __syncthreads();
    // reduce (m,l) across tig lanes
    #pragma unroll
    for (int d = 1; d < 4; d <<= 1) {
        float mo = __shfl_xor_sync(0xffffffffu, m0r, d);
        float lo = __shfl_xor_sync(0xffffffffu, l0r, d);
        float mn = fmaxf(m0r, mo);
        l0r = l0r * __expf(m0r - mn) + lo * __expf(mo - mn); m0r = mn;
        mo = __shfl_xor_sync(0xffffffffu, m1r, d);
        lo = __shfl_xor_sync(0xffffffffu, l1r, d);
        mn = fmaxf(m1r, mo);
        l1r = l1r * __expf(m1r - mn) + lo * __expf(mo - mn); m1r = mn;
    }
    if (tig == 0) {
        pm[rbase * 2 + warpN] = m0r;       pl[rbase * 2 + warpN] = l0r;
        pm[(rbase + 8) * 2 + warpN] = m1r; pl[(rbase + 8) * 2 + warpN] = l1r;
    }
    __syncthreads();
    if (tid < 64) {
        float ma = pm[tid*2], mb_ = pm[tid*2+1], la = pl[tid*2], lb = pl[tid*2+1];
        float mn = fmaxf(ma, mb_);
        lse_s[tid] = mn + logf(la * __expf(ma - mn) + lb * __expf(mb_ - mn));
    }
    __syncthreads();
    // cross-warpN O combine
    if (warpN == 1) {
        #pragma unroll
        for (int ni = 0; ni < 8; ni++) {
            const int d = ni * 8 + tig * 2;
            Obuf[rbase * 66 + d]           = oacc[ni][0];
            Obuf[rbase * 66 + d + 1]       = oacc[ni][1];
            Obuf[(rbase + 8) * 66 + d]     = oacc[ni][2];
            Obuf[(rbase + 8) * 66 + d + 1] = oacc[ni][3];
        }
    }
    __syncthreads();
    if (warpN == 0) {
        const float lse0 = lse_s[rbase], lse1 = lse_s[rbase + 8];
        const int q0r = q0 + rbase;
        #pragma unroll
        for (int ni = 0; ni < 8; ni++) {
            const int d = ni * 8 + tig * 2;
            float2 vt2 = *(const float2*)&g_vt[bh * ND + d];
            float2 sx0 = *(const float2*)&g_sufx[((size_t)bh * NS + q0r    ) * ND + d];
            float2 sx1 = *(const float2*)&g_sufx[((size_t)bh * NS + q0r + 8) * ND + d];
            float2 o0, o1;
            o0.x = oacc[ni][0] + Obuf[rbase * 66 + d]     + NEGV * sx0.x - lse0 * vt2.x;
            o0.y = oacc[ni][1] + Obuf[rbase * 66 + d + 1] + NEGV * sx0.y - lse0 * vt2.y;
            o1.x = oacc[ni][2] + Obuf[(rbase+8) * 66 + d]     + NEGV * sx1.x - lse1 * vt2.x;
            o1.y = oacc[ni][3] + Obuf[(rbase+8) * 66 + d + 1] + NEGV * sx1.y - lse1 * vt2.y;
            *(float2*)&out[(((size_t)b * NS + q0r    ) * NH + h) * ND + d] = o0;
            *(float2*)&out[(((size_t)b * NS + q0r + 8) * NH + h) * ND + d] = o1;
        }
    }
}

// ---------------------------------------------------------------------------
extern "C" void kernel_launch(void* const* d_in, const int* in_sizes, int n_in,
                              void* d_out, int out_size)
{
    (void)in_sizes; (void)n_in; (void)out_size;
    const float* query = (const float*)d_in[0];
    const float* key_  = (const float*)d_in[1];
    const float* value = (const float*)d_in[2];
    const float* Wq    = (const float*)d_in[3];
    const float* bq    = (const float*)d_in[4];
    const float* Wk    = (const float*)d_in[5];
    const float* bk    = (const float*)d_in[6];
    const float* Wv    = (const float*)d_in[7];
    const float* bv    = (const float*)d_in[8];
    const float* pos   = (const float*)d_in[9];

    const int n4x = 4096 * 1024 / 4, n4w = 1024 * 1024 / 4;
    f2bf_kernel<<<n4x / 256, 256>>>((const float4*)query, 0, 0, n4x);
    f2bf_kernel<<<n4x / 256, 256>>>((const float4*)key_,  1, 0, n4x);
    f2bf_kernel<<<n4x / 256, 256>>>((const float4*)value, 2, 1, n4x);
    f2bf_kernel<<<n4w / 256, 256>>>((const float4*)Wq,    4, 0, n4w);
    f2bf_kernel<<<n4w / 256, 256>>>((const float4*)Wk,    5, 0, n4w);
    f2bf_kernel<<<n4w / 256, 256>>>((const float4*)Wv,    6, 1, n4w);

    const int PROJ_SMEM = 4 * 128 * PADW * 2;   // 73728 B (>= 128*131*4 staging)
    cudaFuncSetAttribute(proj_mma, cudaFuncAttributeMaxDynamicSharedMemorySize, PROJ_SMEM);
    proj_mma<<<dim3(8, 32, 3), 256, PROJ_SMEM>>>(bq, bk, bv);

    tile_sum_kernel<<<dim3(NB * NH, NT), 64>>>();
    tile_suffix_kernel<<<dim3(NB * NH), 64>>>();
    row_suffix_kernel<<<dim3(NB * NH, NT), 64>>>();

    const int ATTN_SMEM = 64*PADW*2 + 6*KVBUF*2 + (384 + 128 + 128 + 64) * 4;  // 67328 B
    cudaFuncSetAttribute(attn_mma, cudaFuncAttributeMaxDynamicSharedMemorySize, ATTN_SMEM);
    attn_mma<<<dim3(NT, NH, NB), 256, ATTN_SMEM>>>(pos, (float*)d_out);
}

// round 13
// speedup vs baseline: 1.0361x; 1.0263x over previous
#include <cuda_runtime.h>
#include <cuda_bf16.h>
#include <math.h>
#include <stdint.h>

#define NB 2
#define NS 2048
#define NE 1024
#define NH 16
#define ND 64
#define NT 32            // NS / 64 key tiles
#define NEGV (-1e9f)
#define NEGM (-1e30f)
#define QSCALE 0.125f    // 1/sqrt(64)
#define PADW 72          // bf16 elements per smem row
#define KVBUF (64 * PADW)

// Scratch (allocation-free rule: __device__ globals)
__device__ float g_v[NB*NH*NS*ND];              // fp32 projected V (exact path)
__device__ float g_sufx[NB*NH*NS*ND];           // per-row exclusive suffix: sum_{k>s} v[k][d]
__device__ float g_vt[NB*NH*ND];                // total sum_k v[k][d]
__device__ float g_tsum[NB*NH*NT*ND];           // per-tile V sums
__device__ float g_tsuf[NB*NH*NT*ND];           // exclusive tile-level suffix
__device__ __nv_bfloat16 g_qb[NB*NH*NS*ND];     // bf16 Q (pre-scaled by 1/8)
__device__ __nv_bfloat16 g_kb[NB*NH*NS*ND];     // bf16 K
__device__ __nv_bfloat16 g_vtb[NB*NH*NS*ND];    // bf16 V transposed per 64-tile: [bh][t][d][64]
// bf16 slices: x: 0=query 1=key 2=value_hi 3=value_lo ; w: 0=Wq 1=Wk 2=Wv_hi 3=Wv_lo
__device__ __nv_bfloat16 g_xb[4u*4096*1024];
__device__ __nv_bfloat16 g_wb[4u*1024*1024];

// ---------------------------------------------------------------------------
__device__ __forceinline__ void mma16816(float* c, const uint32_t* a, const uint32_t* b) {
    asm volatile("mma.sync.aligned.m16n8k16.row.col.f32.bf16.bf16.f32 "
        "{%0,%1,%2,%3}, {%4,%5,%6,%7}, {%8,%9}, {%0,%1,%2,%3};"
        : "+f"(c[0]), "+f"(c[1]), "+f"(c[2]), "+f"(c[3])
        : "r"(a[0]), "r"(a[1]), "r"(a[2]), "r"(a[3]), "r"(b[0]), "r"(b[1]));
}
__device__ __forceinline__ void ldsm4(uint32_t& r0, uint32_t& r1, uint32_t& r2, uint32_t& r3,
                                      uint32_t addr) {
    asm volatile("ldmatrix.sync.aligned.m8n8.x4.shared.b16 {%0,%1,%2,%3}, [%4];"
        : "=r"(r0), "=r"(r1), "=r"(r2), "=r"(r3) : "r"(addr));
}
__device__ __forceinline__ uint32_t pack_bf16x2(float a, float b) {
    __nv_bfloat162 t = __floats2bfloat162_rn(a, b);
    return *(uint32_t*)&t;
}
__device__ __forceinline__ uint32_t s2u(const void* p) {
    uint32_t a;
    asm("{ .reg .u64 t; cvta.to.shared.u64 t, %1; cvt.u32.u64 %0, t; }" : "=r"(a) : "l"(p));
    return a;
}
__device__ __forceinline__ void cpa16(uint32_t d, const void* s) {
    asm volatile("cp.async.cg.shared.global [%0], [%1], 16;" :: "r"(d), "l"(s));
}
__device__ __forceinline__ void cpa4(uint32_t d, const void* s) {
    asm volatile("cp.async.ca.shared.global [%0], [%1], 4;" :: "r"(d), "l"(s));
}
#define CP_COMMIT() asm volatile("cp.async.commit_group;" ::: "memory")
#define CP_WAIT1()  asm volatile("cp.async.wait_group 1;" ::: "memory")
#define CP_WAIT0()  asm volatile("cp.async.wait_group 0;" ::: "memory")

// ---------------------------------------------------------------------------
// Kernel 0: fp32 -> bf16 (hi), optionally also residual (lo) into next slice.
// ---------------------------------------------------------------------------
__global__ void f2bf_kernel(const float4* __restrict__ src, int which, int split, int n4)
{
    int i = blockIdx.x * blockDim.x + threadIdx.x;
    if (i >= n4) return;
    __nv_bfloat16* hi = (which < 4)
        ? g_xb + (size_t)which * 4096 * 1024
        : g_wb + (size_t)(which - 4) * 1024 * 1024;
    size_t loOff = (which < 4) ? (size_t)4096 * 1024 : (size_t)1024 * 1024;

    float4 v = src[i];
    __nv_bfloat16 h0 = __float2bfloat16(v.x), h1 = __float2bfloat16(v.y);
    __nv_bfloat16 h2 = __float2bfloat16(v.z), h3 = __float2bfloat16(v.w);
    __nv_bfloat162* dh = (__nv_bfloat162*)hi;
    dh[2*i]   = __nv_bfloat162(h0, h1);
    dh[2*i+1] = __nv_bfloat162(h2, h3);
    if (split) {
        __nv_bfloat162* dl = (__nv_bfloat162*)(hi + loOff);
        dl[2*i]   = __nv_bfloat162(__float2bfloat16(v.x - __bfloat162float(h0)),
                                   __float2bfloat16(v.y - __bfloat162float(h1)));
        dl[2*i+1] = __nv_bfloat162(__float2bfloat16(v.z - __bfloat162float(h2)),
                                   __float2bfloat16(v.w - __bfloat162float(h3)));
    }
}

// ---------------------------------------------------------------------------
// Kernel 1: projections via mma.sync bf16.  2 heads per block (N=128).
// z = 0: Q -> g_qb bf16 (scaled), 1: K -> g_kb, 2: V (3-mma split) -> g_v fp32 + g_vtb bf16^T
// 8 warps = 4(m) x 2(n); warp tile 32(m) x 64(n); K-chunk 64.
// ---------------------------------------------------------------------------
__global__ __launch_bounds__(256) void proj_mma(
    const float* __restrict__ bq, const float* __restrict__ bk, const float* __restrict__ bv)
{
    extern __shared__ __align__(16) char smraw[];
    __nv_bfloat16* Xh = (__nv_bfloat16*)smraw;       // [128][PADW]
    __nv_bfloat16* Wh = Xh + 128 * PADW;             // [128][PADW] (2 heads)
    __nv_bfloat16* Xl = Wh + 128 * PADW;             // (V only)
    __nv_bfloat16* Wl = Xl + 128 * PADW;             // (V only)

    const int z = blockIdx.z;
    const int split = (z == 2);
    const __nv_bfloat16* Xg  = g_xb + (size_t)z * 4096 * 1024;
    const __nv_bfloat16* Wg  = g_wb + (size_t)z * 1024 * 1024;
    const __nv_bfloat16* XgL = g_xb + (size_t)3 * 4096 * 1024;
    const __nv_bfloat16* WgL = g_wb + (size_t)3 * 1024 * 1024;
    const float* bias = (z == 0) ? bq : (z == 1) ? bk : bv;

    const int hp = blockIdx.x;                  // head pair 0..7
    const int m0 = blockIdx.y * 128;
    const int tid = threadIdx.x;
    const int wid = tid >> 5, lane = tid & 31;
    const int warpM = wid >> 1, warpN = wid & 1;
    const int gp = lane >> 2, tig = lane & 3;

    float acc[2][8][4] = {};

    for (int c = 0; c < 16; c++) {
        const int k0 = c * 64;
        __syncthreads();
        #pragma unroll
        for (int j = 0; j < 4; j++) {
            int u = tid + j * 256;
            int r = u >> 3, cg = (u & 7) * 8;
            *(uint4*)&Xh[r * PADW + cg] = *(const uint4*)(Xg + (size_t)(m0 + r) * NE + k0 + cg);
            *(uint4*)&Wh[r * PADW + cg] = *(const uint4*)(Wg + (size_t)(hp * 128 + r) * NE + k0 + cg);
            if (split) {
                *(uint4*)&Xl[r * PADW + cg] = *(const uint4*)(XgL + (size_t)(m0 + r) * NE + k0 + cg);
                *(uint4*)&Wl[r * PADW + cg] = *(const uint4*)(WgL + (size_t)(hp * 128 + r) * NE + k0 + cg);
            }
        }
        __syncthreads();

        #pragma unroll
        for (int ks = 0; ks < 4; ks++) {
            const int kc = ks * 16 + tig * 2;
            uint32_t a[2][4], al[2][4];
            #pragma unroll
            for (int mi = 0; mi < 2; mi++) {
                const int r = warpM * 32 + mi * 16 + gp;
                a[mi][0] = *(const uint32_t*)&Xh[(r    ) * PADW + kc];
                a[mi][1] = *(const uint32_t*)&Xh[(r + 8) * PADW + kc];
                a[mi][2] = *(const uint32_t*)&Xh[(r    ) * PADW + kc + 8];
                a[mi][3] = *(const uint32_t*)&Xh[(r + 8) * PADW + kc + 8];
                if (split) {
                    al[mi][0] = *(const uint32_t*)&Xl[(r    ) * PADW + kc];
                    al[mi][1] = *(const uint32_t*)&Xl[(r + 8) * PADW + kc];
                    al[mi][2] = *(const uint32_t*)&Xl[(r    ) * PADW + kc + 8];
                    al[mi][3] = *(const uint32_t*)&Xl[(r + 8) * PADW + kc + 8];
                }
            }
            #pragma unroll
            for (int ni = 0; ni < 8; ni++) {
                const int n = warpN * 64 + ni * 8 + gp;
                uint32_t b[2], bl[2];
                b[0] = *(const uint32_t*)&Wh[n * PADW + kc];
                b[1] = *(const uint32_t*)&Wh[n * PADW + kc + 8];
                if (split) {
                    bl[0] = *(const uint32_t*)&Wl[n * PADW + kc];
                    bl[1] = *(const uint32_t*)&Wl[n * PADW + kc + 8];
                }
                #pragma unroll
                for (int mi = 0; mi < 2; mi++) {
                    mma16816(acc[mi][ni], a[mi], b);
                    if (split) {
                        mma16816(acc[mi][ni], a[mi], bl);
                        mma16816(acc[mi][ni], al[mi], b);
                    }
                }
            }
        }
    }

    const int b  = m0 >> 11;
    const int s0 = m0 & (NS - 1);
    __syncthreads();

    if (z < 2) {
        const float sc = (z == 0) ? QSCALE : 1.0f;
        __nv_bfloat16* dst = (z == 0) ? g_qb : g_kb;
        const int head = hp * 2 + warpN;
        const size_t bh = (size_t)(b * NH + head);
        #pragma unroll
        for (int mi = 0; mi < 2; mi++)
            #pragma unroll
            for (int ni = 0; ni < 8; ni++) {
                const int r = warpM * 32 + mi * 16 + gp;
                const int d = ni * 8 + tig * 2;
                const float bx = bias[head * 64 + d], by = bias[head * 64 + d + 1];
                #pragma unroll
                for (int half = 0; half < 2; half++) {
                    const int s = s0 + r + half * 8;
                    float v0 = (acc[mi][ni][2*half+0] + bx) * sc;
                    float v1 = (acc[mi][ni][2*half+1] + by) * sc;
                    *(uint32_t*)&dst[(bh * NS + s) * ND + d] = pack_bf16x2(v0, v1);
                }
            }
    } else {
        float* Vst = (float*)smraw;    // [128][131] staging
        #pragma unroll
        for (int mi = 0; mi < 2; mi++)
            #pragma unroll
            for (int ni = 0; ni < 8; ni++) {
                const int r = warpM * 32 + mi * 16 + gp;
                const int cn = warpN * 64 + ni * 8 + tig * 2;
                const float bx = bias[hp * 128 + cn], by = bias[hp * 128 + cn + 1];
                #pragma unroll
                for (int half = 0; half < 2; half++) {
                    const int rr = r + half * 8;
                    Vst[rr * 131 + cn    ] = acc[mi][ni][2*half+0] + bx;
                    Vst[rr * 131 + cn + 1] = acc[mi][ni][2*half+1] + by;
                }
            }
        __syncthreads();
        // coalesced fp32 V (2 heads)
        #pragma unroll
        for (int i = 0; i < 16; i++) {
            int u = tid + i * 256;
            int r = u >> 5, c4 = (u & 31) * 4;
            int head = hp * 2 + (c4 >> 6), d = c4 & 63;
            float4 w = make_float4(Vst[r*131+c4], Vst[r*131+c4+1], Vst[r*131+c4+2], Vst[r*131+c4+3]);
            *(float4*)&g_v[((size_t)(b * NH + head) * NS + s0 + r) * ND + d] = w;
        }
        // coalesced transposed bf16 V
        const int t0 = s0 >> 6;
        #pragma unroll
        for (int i = 0; i < 32; i++) {
            int u = tid + i * 256;
            int j = (u & 31) * 2, cc = (u >> 5) & 127, tl = u >> 12;
            int head = hp * 2 + (cc >> 6), d = cc & 63;
            uint32_t p = pack_bf16x2(Vst[(tl*64 + j)*131 + cc], Vst[(tl*64 + j + 1)*131 + cc]);
            *(uint32_t*)&g_vtb[(((size_t)(b * NH + head) * NT + t0 + tl) * ND + d) * 64 + j] = p;
        }
    }
}

// ---------------------------------------------------------------------------
// Kernels 2a/2b/2c: parallel per-row exclusive suffix sums (register-buffered).
// ---------------------------------------------------------------------------
__global__ void tile_sum_kernel()
{
    const int bh = blockIdx.x, t = blockIdx.y, d = threadIdx.x;
    const float* v = g_v + ((size_t)bh * NS + t * 64) * ND + d;
    float vals[64];
    #pragma unroll
    for (int j = 0; j < 64; j++) vals[j] = v[(size_t)j * ND];
    float a = 0.f;
    #pragma unroll
    for (int j = 0; j < 64; j++) a += vals[j];
    g_tsum[((size_t)bh * NT + t) * ND + d] = a;
}
__global__ void tile_suffix_kernel()
{
    const int bh = blockIdx.x, d = threadIdx.x;
    float vals[NT];
    #pragma unroll
    for (int t = 0; t < NT; t++) vals[t] = g_tsum[((size_t)bh * NT + t) * ND + d];
    float acc = 0.f;
    #pragma unroll
    for (int t = NT - 1; t >= 0; t--) {
        g_tsuf[((size_t)bh * NT + t) * ND + d] = acc;
        acc += vals[t];
    }
    g_vt[bh * ND + d] = acc;
}
__global__ void row_suffix_kernel()
{
    const int bh = blockIdx.x, t = blockIdx.y, d = threadIdx.x;
    const float* v = g_v + ((size_t)bh * NS + t * 64) * ND + d;
    float vals[64];
    #pragma unroll
    for (int j = 0; j < 64; j++) vals[j] = v[(size_t)j * ND];
    float acc = g_tsuf[((size_t)bh * NT + t) * ND + d];
    float* sx = g_sufx + ((size_t)bh * NS + t * 64) * ND + d;
    #pragma unroll
    for (int j = 63; j >= 0; j--) {
        sx[(size_t)j * ND] = acc;
        acc += vals[j];
    }
}

// ---------------------------------------------------------------------------
// Kernel 3: register-resident flash attention, 3-stage cp.async pipeline,
// ldmatrix.x4 fragment loads (16 LDSM replace 64 LDS.32 per thread per tile).
// ---------------------------------------------------------------------------
__global__ __launch_bounds__(256, 2) void attn_mma(
    const float* __restrict__ pos_bias, float* __restrict__ out)
{
    extern __shared__ __align__(16) char smr[];
    __nv_bfloat16* Qb  = (__nv_bfloat16*)smr;        // [64][72]
    __nv_bfloat16* KV0 = Qb + 64 * PADW;             // 3 slots x (K,V), each 64*PADW
    float* posw  = (float*)(KV0 + 6 * KVBUF);        // [3][128]
    float* pm    = posw + 384;                       // [64][2]
    float* pl    = pm + 128;                         // [64][2]
    float* lse_s = pl + 128;                         // [64]
    float* Obuf  = (float*)smr;                      // overlay [64][66]

    const int tq = NT - 1 - blockIdx.x;              // heavy blocks first
    const int h  = blockIdx.y;
    const int b  = blockIdx.z;
    const int bh = b * NH + h;
    const int q0 = tq * 64;
    const int tid = threadIdx.x;
    const int wid = tid >> 5, lane = tid & 31;
    const int warpM = wid >> 1, warpN = wid & 1;
    const int gp = lane >> 2, tig = lane & 3;
    const int rbase = warpM * 16 + gp;

    // ldmatrix lane-relative offsets (loop-invariant, bytes)
    const int mrow = (lane & 7) | ((lane >> 4) << 3);   // row within 16-row group
    const int ksub = (lane >> 3) & 1;                   // k-subtile (0: k0..7, 1: k8..15)
    uint32_t qk_off[2], sv_off[4];
    #pragma unroll
    for (int g = 0; g < 2; g++)
        qk_off[g] = ((warpN * 32 + g * 16 + mrow) * PADW + ksub * 8) * 2;
    #pragma unroll
    for (int g2 = 0; g2 < 4; g2++)
        sv_off[g2] = ((g2 * 16 + mrow) * PADW + warpN * 32 + ksub * 8) * 2;

    auto prefetch = [&](int t, int s) {
        const int k0 = t * 64;
        __nv_bfloat16* Ks = KV0 + s * 2 * KVBUF;
        __nv_bfloat16* Vs = Ks + KVBUF;
        #pragma unroll
        for (int j = 0; j < 2; j++) {
            int u = tid + j * 256;
            int r = u >> 3, cg = (u & 7) * 8;
            cpa16(s2u(&Ks[r * PADW + cg]), g_kb + ((size_t)bh * NS + k0 + r) * ND + cg);
            cpa16(s2u(&Vs[r * PADW + cg]), g_vtb + (((size_t)bh * NT + t) * ND + r) * 64 + cg);
        }
        if (tid < 128) {
            int idx = q0 - k0 - 63 + tid + NS - 1;
            if (idx <= 2 * NS - 2)
                cpa4(s2u(&posw[s * 128 + tid]), &pos_bias[(size_t)h * (2 * NS - 1) + idx]);
            else
                posw[s * 128 + tid] = 0.f;
        }
    };

    prefetch(0, 0); CP_COMMIT();
    if (tq >= 1) prefetch(1, 1);
    CP_COMMIT();

    // Q tile -> smem -> fragments (resident all tiles)
    #pragma unroll
    for (int j = 0; j < 2; j++) {
        int u = tid + j * 256;
        int r = u >> 3, cg = (u & 7) * 8;
        *(uint4*)&Qb[r * PADW + cg] = *(const uint4*)(g_qb + ((size_t)bh * NS + q0 + r) * ND + cg);
    }
    __syncthreads();
    uint32_t aq[4][4];
    #pragma unroll
    for (int ks = 0; ks < 4; ks++) {
        const int kc = ks * 16 + tig * 2;
        aq[ks][0] = *(const uint32_t*)&Qb[(rbase    ) * PADW + kc];
        aq[ks][1] = *(const uint32_t*)&Qb[(rbase + 8) * PADW + kc];
        aq[ks][2] = *(const uint32_t*)&Qb[(rbase    ) * PADW + kc + 8];
        aq[ks][3] = *(const uint32_t*)&Qb[(rbase + 8) * PADW + kc + 8];
    }

    float oacc[8][4] = {};
    float m0r = NEGM, l0r = 0.f, m1r = NEGM, l1r = 0.f;

    for (int t = 0; t <= tq; t++) {
        const bool diag = (t == tq);
        const int s = t % 3;
        CP_WAIT1();
        __syncthreads();
        if (t + 2 <= tq) prefetch(t + 2, (t + 2) % 3);
        CP_COMMIT();

        const __nv_bfloat16* Ks = KV0 + s * 2 * KVBUF;
        const __nv_bfloat16* Vs = Ks + KVBUF;
        const float* pw = posw + s * 128;
        const uint32_t ksaddr = s2u(Ks);
        const uint32_t vsaddr = s2u(Vs);

        // ---- S = Q.K^T over this warp's k-half (ldmatrix B-frags) ----
        float cS[4][4] = {};
        #pragma unroll
        for (int ks = 0; ks < 4; ks++) {
            uint32_t bb[4][2];
            #pragma unroll
            for (int g = 0; g < 2; g++)
                ldsm4(bb[g*2][0], bb[g*2][1], bb[g*2+1][0], bb[g*2+1][1],
                      ksaddr + qk_off[g] + ks * 32);
            #pragma unroll
            for (int ni = 0; ni < 4; ni++) mma16816(cS[ni], aq[ks], bb[ni]);
        }

        // ---- bias + mask in registers; pack SV A-frags; lse values ----
        float e0[8], e1[8];
        uint32_t sf[2][4];
        #pragma unroll
        for (int ni = 0; ni < 4; ni++) {
            const int kcol = warpN * 32 + ni * 8 + tig * 2;
            float v00 = cS[ni][0] + pw[rbase     - kcol + 63];
            float v01 = cS[ni][1] + pw[rbase     - kcol + 62];
            float v10 = cS[ni][2] + pw[rbase + 8 - kcol + 63];
            float v11 = cS[ni][3] + pw[rbase + 8 - kcol + 62];
            float p00 = v00, p01 = v01, p10 = v10, p11 = v11;
            if (diag) {
                if (kcol     > rbase)     { v00 = NEGM; p00 = 0.f; }
                if (kcol + 1 > rbase)     { v01 = NEGM; p01 = 0.f; }
                if (kcol     > rbase + 8) { v10 = NEGM; p10 = 0.f; }
                if (kcol + 1 > rbase + 8) { v11 = NEGM; p11 = 0.f; }
            }
            e0[ni*2] = v00; e0[ni*2+1] = v01;
            e1[ni*2] = v10; e1[ni*2+1] = v11;
            const int ks2 = ni >> 1;
            if ((ni & 1) == 0) {
                sf[ks2][0] = pack_bf16x2(p00, p01);
                sf[ks2][1] = pack_bf16x2(p10, p11);
            } else {
                sf[ks2][2] = pack_bf16x2(p00, p01);
                sf[ks2][3] = pack_bf16x2(p10, p11);
            }
        }
        // ---- online lse (register-only) ----
        {
            float vm = e0[0];
            #pragma unroll
            for (int j = 1; j < 8; j++) vm = fmaxf(vm, e0[j]);
            float mn = fmaxf(m0r, vm);
            float sum = 0.f;
            #pragma unroll
            for (int j = 0; j < 8; j++) sum += __expf(e0[j] - mn);
            l0r = l0r * __expf(m0r - mn) + sum; m0r = mn;
        }
        {
            float vm = e1[0];
            #pragma unroll
            for (int j = 1; j < 8; j++) vm = fmaxf(vm, e1[j]);
            float mn = fmaxf(m1r, vm);
            float sum = 0.f;
            #pragma unroll
            for (int j = 0; j < 8; j++) sum += __expf(e1[j] - mn);
            l1r = l1r * __expf(m1r - mn) + sum; m1r = mn;
        }

        // ---- O += S.V over this warp's k-half (ldmatrix B-frags, full 64 d) ----
        #pragma unroll
        for (int ks2 = 0; ks2 < 2; ks2++) {
            #pragma unroll
            for (int g2 = 0; g2 < 4; g2++) {
                uint32_t t0, t1, t2, t3;
                ldsm4(t0, t1, t2, t3, vsaddr + sv_off[g2] + ks2 * 32);
                uint32_t ba[2] = {t0, t1}, bc[2] = {t2, t3};
                mma16816(oacc[g2*2    ], sf[ks2], ba);
                mma16816(oacc[g2*2 + 1], sf[ks2], bc);
            }
        }
    }

    CP_WAIT0();
    __syncthreads();
    // reduce (m,l) across tig lanes
    #pragma unroll
    for (int d = 1; d < 4; d <<= 1) {
        float mo = __shfl_xor_sync(0xffffffffu, m0r, d);
        float lo = __shfl_xor_sync(0xffffffffu, l0r, d);
        float mn = fmaxf(m0r, mo);
        l0r = l0r * __expf(m0r - mn) + lo * __expf(mo - mn); m0r = mn;
        mo = __shfl_xor_sync(0xffffffffu, m1r, d);
        lo = __shfl_xor_sync(0xffffffffu, l1r, d);
        mn = fmaxf(m1r, mo);
        l1r = l1r * __expf(m1r - mn) + lo * __expf(mo - mn); m1r = mn;
    }
    if (tig == 0) {
        pm[rbase * 2 + warpN] = m0r;       pl[rbase * 2 + warpN] = l0r;
        pm[(rbase + 8) * 2 + warpN] = m1r; pl[(rbase + 8) * 2 + warpN] = l1r;
    }
    __syncthreads();
    if (tid < 64) {
        float ma = pm[tid*2], mb_ = pm[tid*2+1], la = pl[tid*2], lb = pl[tid*2+1];
        float mn = fmaxf(ma, mb_);
        lse_s[tid] = mn + logf(la * __expf(ma - mn) + lb * __expf(mb_ - mn));
    }
    __syncthreads();
    // cross-warpN O combine
    if (warpN == 1) {
        #pragma unroll
        for (int ni = 0; ni < 8; ni++) {
            const int d = ni * 8 + tig * 2;
            Obuf[rbase * 66 + d]           = oacc[ni][0];
            Obuf[rbase * 66 + d + 1]       = oacc[ni][1];
            Obuf[(rbase + 8) * 66 + d]     = oacc[ni][2];
            Obuf[(rbase + 8) * 66 + d + 1] = oacc[ni][3];
        }
    }
    __syncthreads();
    if (warpN == 0) {
        const float lse0 = lse_s[rbase], lse1 = lse_s[rbase + 8];
        const int q0r = q0 + rbase;
        #pragma unroll
        for (int ni = 0; ni < 8; ni++) {
            const int d = ni * 8 + tig * 2;
            float2 vt2 = *(const float2*)&g_vt[bh * ND + d];
            float2 sx0 = *(const float2*)&g_sufx[((size_t)bh * NS + q0r    ) * ND + d];
            float2 sx1 = *(const float2*)&g_sufx[((size_t)bh * NS + q0r + 8) * ND + d];
            float2 o0, o1;
            o0.x = oacc[ni][0] + Obuf[rbase * 66 + d]     + NEGV * sx0.x - lse0 * vt2.x;
            o0.y = oacc[ni][1] + Obuf[rbase * 66 + d + 1] + NEGV * sx0.y - lse0 * vt2.y;
            o1.x = oacc[ni][2] + Obuf[(rbase+8) * 66 + d]     + NEGV * sx1.x - lse1 * vt2.x;
            o1.y = oacc[ni][3] + Obuf[(rbase+8) * 66 + d + 1] + NEGV * sx1.y - lse1 * vt2.y;
            *(float2*)&out[(((size_t)b * NS + q0r    ) * NH + h) * ND + d] = o0;
            *(float2*)&out[(((size_t)b * NS + q0r + 8) * NH + h) * ND + d] = o1;
        }
    }
}

// ---------------------------------------------------------------------------
extern "C" void kernel_launch(void* const* d_in, const int* in_sizes, int n_in,
                              void* d_out, int out_size)
{
    (void)in_sizes; (void)n_in; (void)out_size;
    const float* query = (const float*)d_in[0];
    const float* key_  = (const float*)d_in[1];
    const float* value = (const float*)d_in[2];
    const float* Wq    = (const float*)d_in[3];
    const float* bq    = (const float*)d_in[4];
    const float* Wk    = (const float*)d_in[5];
    const float* bk    = (const float*)d_in[6];
    const float* Wv    = (const float*)d_in[7];
    const float* bv    = (const float*)d_in[8];
    const float* pos   = (const float*)d_in[9];

    const int n4x = 4096 * 1024 / 4, n4w = 1024 * 1024 / 4;
    f2bf_kernel<<<n4x / 256, 256>>>((const float4*)query, 0, 0, n4x);
    f2bf_kernel<<<n4x / 256, 256>>>((const float4*)key_,  1, 0, n4x);
    f2bf_kernel<<<n4x / 256, 256>>>((const float4*)value, 2, 1, n4x);
    f2bf_kernel<<<n4w / 256, 256>>>((const float4*)Wq,    4, 0, n4w);
    f2bf_kernel<<<n4w / 256, 256>>>((const float4*)Wk,    5, 0, n4w);
    f2bf_kernel<<<n4w / 256, 256>>>((const float4*)Wv,    6, 1, n4w);

    const int PROJ_SMEM = 4 * 128 * PADW * 2;   // 73728 B (>= 128*131*4 staging)
    cudaFuncSetAttribute(proj_mma, cudaFuncAttributeMaxDynamicSharedMemorySize, PROJ_SMEM);
    proj_mma<<<dim3(8, 32, 3), 256, PROJ_SMEM>>>(bq, bk, bv);

    tile_sum_kernel<<<dim3(NB * NH, NT), 64>>>();
    tile_suffix_kernel<<<dim3(NB * NH), 64>>>();
    row_suffix_kernel<<<dim3(NB * NH, NT), 64>>>();

    const int ATTN_SMEM = 64*PADW*2 + 6*KVBUF*2 + (384 + 128 + 128 + 64) * 4;  // 67328 B
    cudaFuncSetAttribute(attn_mma, cudaFuncAttributeMaxDynamicSharedMemorySize, ATTN_SMEM);
    attn_mma<<<dim3(NT, NH, NB), 256, ATTN_SMEM>>>(pos, (float*)d_out);
}

// round 14
// speedup vs baseline: 1.2261x; 1.1834x over previous
#include <cuda_runtime.h>
#include <cuda_bf16.h>
#include <math.h>
#include <stdint.h>

#define NB 2
#define NS 2048
#define NE 1024
#define NH 16
#define ND 64
#define NT 32            // NS / 64 key tiles
#define NEGV (-1e9f)
#define NEGM (-1e30f)
#define QSCALE 0.125f    // 1/sqrt(64)
#define PADW 72          // bf16 elements per smem row
#define KVBUF (64 * PADW)
#define TILE_B (128 * PADW * 2)   // 18432 B: one 128x64 bf16 tile in smem

// Scratch (allocation-free rule: __device__ globals)
__device__ float g_v[NB*NH*NS*ND];              // fp32 projected V (exact path)
__device__ float g_sufx[NB*NH*NS*ND];           // per-row exclusive suffix: sum_{k>s} v[k][d]
__device__ float g_vt[NB*NH*ND];                // total sum_k v[k][d]
__device__ float g_tsum[NB*NH*NT*ND];           // per-tile V sums
__device__ float g_tsuf[NB*NH*NT*ND];           // exclusive tile-level suffix
__device__ __nv_bfloat16 g_qb[NB*NH*NS*ND];     // bf16 Q (pre-scaled by 1/8)
__device__ __nv_bfloat16 g_kb[NB*NH*NS*ND];     // bf16 K
__device__ __nv_bfloat16 g_vtb[NB*NH*NS*ND];    // bf16 V transposed per 64-tile: [bh][t][d][64]
// bf16 slices: x: 0=query 1=key 2=value_hi 3=value_lo ; w: 0=Wq 1=Wk 2=Wv_hi 3=Wv_lo
__device__ __nv_bfloat16 g_xb[4u*4096*1024];
__device__ __nv_bfloat16 g_wb[4u*1024*1024];

// ---------------------------------------------------------------------------
__device__ __forceinline__ void mma16816(float* c, const uint32_t* a, const uint32_t* b) {
    asm volatile("mma.sync.aligned.m16n8k16.row.col.f32.bf16.bf16.f32 "
        "{%0,%1,%2,%3}, {%4,%5,%6,%7}, {%8,%9}, {%0,%1,%2,%3};"
        : "+f"(c[0]), "+f"(c[1]), "+f"(c[2]), "+f"(c[3])
        : "r"(a[0]), "r"(a[1]), "r"(a[2]), "r"(a[3]), "r"(b[0]), "r"(b[1]));
}
__device__ __forceinline__ void ldsm4(uint32_t& r0, uint32_t& r1, uint32_t& r2, uint32_t& r3,
                                      uint32_t addr) {
    asm volatile("ldmatrix.sync.aligned.m8n8.x4.shared.b16 {%0,%1,%2,%3}, [%4];"
        : "=r"(r0), "=r"(r1), "=r"(r2), "=r"(r3) : "r"(addr));
}
__device__ __forceinline__ uint32_t pack_bf16x2(float a, float b) {
    __nv_bfloat162 t = __floats2bfloat162_rn(a, b);
    return *(uint32_t*)&t;
}
__device__ __forceinline__ uint32_t s2u(const void* p) {
    uint32_t a;
    asm("{ .reg .u64 t; cvta.to.shared.u64 t, %1; cvt.u32.u64 %0, t; }" : "=r"(a) : "l"(p));
    return a;
}
__device__ __forceinline__ void cpa16(uint32_t d, const void* s) {
    asm volatile("cp.async.cg.shared.global [%0], [%1], 16;" :: "r"(d), "l"(s));
}
__device__ __forceinline__ void cpa4(uint32_t d, const void* s) {
    asm volatile("cp.async.ca.shared.global [%0], [%1], 4;" :: "r"(d), "l"(s));
}
#define CP_COMMIT() asm volatile("cp.async.commit_group;" ::: "memory")
#define CP_WAIT1()  asm volatile("cp.async.wait_group 1;" ::: "memory")
#define CP_WAIT0()  asm volatile("cp.async.wait_group 0;" ::: "memory")

// ---------------------------------------------------------------------------
// Kernel 0: fp32 -> bf16 (hi), optionally also residual (lo) into next slice.
// ---------------------------------------------------------------------------
__global__ void f2bf_kernel(const float4* __restrict__ src, int which, int split, int n4)
{
    int i = blockIdx.x * blockDim.x + threadIdx.x;
    if (i >= n4) return;
    __nv_bfloat16* hi = (which < 4)
        ? g_xb + (size_t)which * 4096 * 1024
        : g_wb + (size_t)(which - 4) * 1024 * 1024;
    size_t loOff = (which < 4) ? (size_t)4096 * 1024 : (size_t)1024 * 1024;

    float4 v = src[i];
    __nv_bfloat16 h0 = __float2bfloat16(v.x), h1 = __float2bfloat16(v.y);
    __nv_bfloat16 h2 = __float2bfloat16(v.z), h3 = __float2bfloat16(v.w);
    __nv_bfloat162* dh = (__nv_bfloat162*)hi;
    dh[2*i]   = __nv_bfloat162(h0, h1);
    dh[2*i+1] = __nv_bfloat162(h2, h3);
    if (split) {
        __nv_bfloat162* dl = (__nv_bfloat162*)(hi + loOff);
        dl[2*i]   = __nv_bfloat162(__float2bfloat16(v.x - __bfloat162float(h0)),
                                   __float2bfloat16(v.y - __bfloat162float(h1)));
        dl[2*i+1] = __nv_bfloat162(__float2bfloat16(v.z - __bfloat162float(h2)),
                                   __float2bfloat16(v.w - __bfloat162float(h3)));
    }
}

// ---------------------------------------------------------------------------
// Kernel 1a: Q/K projections, 2-stage cp.async double-buffered.
// z = 0: Q -> g_qb bf16 (scaled), 1: K -> g_kb.
// stage layout: [st*2*TILE_B] = X tile, +TILE_B = W tile.
// ---------------------------------------------------------------------------
__global__ __launch_bounds__(256) void proj_qk(
    const float* __restrict__ bq, const float* __restrict__ bk)
{
    extern __shared__ __align__(16) char smraw[];

    const int z = blockIdx.z;
    const __nv_bfloat16* Xg = g_xb + (size_t)z * 4096 * 1024;
    const __nv_bfloat16* Wg = g_wb + (size_t)z * 1024 * 1024;
    const float* bias = z ? bk : bq;

    const int hp = blockIdx.x;                  // head pair 0..7
    const int m0 = blockIdx.y * 128;
    const int tid = threadIdx.x;
    const int wid = tid >> 5, lane = tid & 31;
    const int warpM = wid >> 1, warpN = wid & 1;
    const int gp = lane >> 2, tig = lane & 3;

    auto prefetch = [&](int c) {
        const int st = c & 1;
        __nv_bfloat16* Xh = (__nv_bfloat16*)(smraw + st * 2 * TILE_B);
        __nv_bfloat16* Wh = Xh + 128 * PADW;
        const int k0 = c * 64;
        #pragma unroll
        for (int j = 0; j < 4; j++) {
            int u = tid + j * 256;
            int r = u >> 3, cg = (u & 7) * 8;
            cpa16(s2u(&Xh[r * PADW + cg]), Xg + (size_t)(m0 + r) * NE + k0 + cg);
            cpa16(s2u(&Wh[r * PADW + cg]), Wg + (size_t)(hp * 128 + r) * NE + k0 + cg);
        }
    };

    prefetch(0); CP_COMMIT();

    float acc[2][8][4] = {};

    for (int c = 0; c < 16; c++) {
        if (c < 15) { prefetch(c + 1); CP_COMMIT(); CP_WAIT1(); }
        else        { CP_WAIT0(); }
        __syncthreads();

        const int st = c & 1;
        const __nv_bfloat16* Xh = (const __nv_bfloat16*)(smraw + st * 2 * TILE_B);
        const __nv_bfloat16* Wh = Xh + 128 * PADW;

        #pragma unroll
        for (int ks = 0; ks < 4; ks++) {
            const int kc = ks * 16 + tig * 2;
            uint32_t a[2][4];
            #pragma unroll
            for (int mi = 0; mi < 2; mi++) {
                const int r = warpM * 32 + mi * 16 + gp;
                a[mi][0] = *(const uint32_t*)&Xh[(r    ) * PADW + kc];
                a[mi][1] = *(const uint32_t*)&Xh[(r + 8) * PADW + kc];
                a[mi][2] = *(const uint32_t*)&Xh[(r    ) * PADW + kc + 8];
                a[mi][3] = *(const uint32_t*)&Xh[(r + 8) * PADW + kc + 8];
            }
            #pragma unroll
            for (int ni = 0; ni < 8; ni++) {
                const int n = warpN * 64 + ni * 8 + gp;
                uint32_t b[2];
                b[0] = *(const uint32_t*)&Wh[n * PADW + kc];
                b[1] = *(const uint32_t*)&Wh[n * PADW + kc + 8];
                #pragma unroll
                for (int mi = 0; mi < 2; mi++) mma16816(acc[mi][ni], a[mi], b);
            }
        }
        __syncthreads();   // stage free before it is refilled at c+2's prefetch
    }

    const int b  = m0 >> 11;
    const int s0 = m0 & (NS - 1);
    const float sc = (z == 0) ? QSCALE : 1.0f;
    __nv_bfloat16* dst = (z == 0) ? g_qb : g_kb;
    const int head = hp * 2 + warpN;
    const size_t bh = (size_t)(b * NH + head);
    #pragma unroll
    for (int mi = 0; mi < 2; mi++)
        #pragma unroll
        for (int ni = 0; ni < 8; ni++) {
            const int r = warpM * 32 + mi * 16 + gp;
            const int d = ni * 8 + tig * 2;
            const float bx = bias[head * 64 + d], by = bias[head * 64 + d + 1];
            #pragma unroll
            for (int half = 0; half < 2; half++) {
                const int s = s0 + r + half * 8;
                float v0 = (acc[mi][ni][2*half+0] + bx) * sc;
                float v1 = (acc[mi][ni][2*half+1] + by) * sc;
                *(uint32_t*)&dst[(bh * NS + s) * ND + d] = pack_bf16x2(v0, v1);
            }
        }
}

// ---------------------------------------------------------------------------
// Kernel 1b: V projection (3-mma split-precision), 2-stage cp.async pipeline.
// stage layout: [st*4*TILE_B] = Xh, +TILE_B = Wh, +2*TILE_B = Xl, +3*TILE_B = Wl.
// ---------------------------------------------------------------------------
__global__ __launch_bounds__(256) void proj_v(const float* __restrict__ bv)
{
    extern __shared__ __align__(16) char smraw[];

    const __nv_bfloat16* Xg  = g_xb + (size_t)2 * 4096 * 1024;
    const __nv_bfloat16* Wg  = g_wb + (size_t)2 * 1024 * 1024;
    const __nv_bfloat16* XgL = g_xb + (size_t)3 * 4096 * 1024;
    const __nv_bfloat16* WgL = g_wb + (size_t)3 * 1024 * 1024;

    const int hp = blockIdx.x;
    const int m0 = blockIdx.y * 128;
    const int tid = threadIdx.x;
    const int wid = tid >> 5, lane = tid & 31;
    const int warpM = wid >> 1, warpN = wid & 1;
    const int gp = lane >> 2, tig = lane & 3;

    auto prefetch = [&](int c) {
        const int st = c & 1;
        __nv_bfloat16* Xh = (__nv_bfloat16*)(smraw + st * 4 * TILE_B);
        __nv_bfloat16* Wh = Xh + 128 * PADW;
        __nv_bfloat16* Xl = Wh + 128 * PADW;
        __nv_bfloat16* Wl = Xl + 128 * PADW;
        const int k0 = c * 64;
        #pragma unroll
        for (int j = 0; j < 4; j++) {
            int u = tid + j * 256;
            int r = u >> 3, cg = (u & 7) * 8;
            cpa16(s2u(&Xh[r * PADW + cg]), Xg  + (size_t)(m0 + r) * NE + k0 + cg);
            cpa16(s2u(&Wh[r * PADW + cg]), Wg  + (size_t)(hp * 128 + r) * NE + k0 + cg);
            cpa16(s2u(&Xl[r * PADW + cg]), XgL + (size_t)(m0 + r) * NE + k0 + cg);
            cpa16(s2u(&Wl[r * PADW + cg]), WgL + (size_t)(hp * 128 + r) * NE + k0 + cg);
        }
    };

    prefetch(0); CP_COMMIT();

    float acc[2][8][4] = {};

    for (int c = 0; c < 16; c++) {
        if (c < 15) { prefetch(c + 1); CP_COMMIT(); CP_WAIT1(); }
        else        { CP_WAIT0(); }
        __syncthreads();

        const int st = c & 1;
        const __nv_bfloat16* Xh = (const __nv_bfloat16*)(smraw + st * 4 * TILE_B);
        const __nv_bfloat16* Wh = Xh + 128 * PADW;
        const __nv_bfloat16* Xl = Wh + 128 * PADW;
        const __nv_bfloat16* Wl = Xl + 128 * PADW;

        #pragma unroll
        for (int ks = 0; ks < 4; ks++) {
            const int kc = ks * 16 + tig * 2;
            uint32_t a[2][4], al[2][4];
            #pragma unroll
            for (int mi = 0; mi < 2; mi++) {
                const int r = warpM * 32 + mi * 16 + gp;
                a[mi][0] = *(const uint32_t*)&Xh[(r    ) * PADW + kc];
                a[mi][1] = *(const uint32_t*)&Xh[(r + 8) * PADW + kc];
                a[mi][2] = *(const uint32_t*)&Xh[(r    ) * PADW + kc + 8];
                a[mi][3] = *(const uint32_t*)&Xh[(r + 8) * PADW + kc + 8];
                al[mi][0] = *(const uint32_t*)&Xl[(r    ) * PADW + kc];
                al[mi][1] = *(const uint32_t*)&Xl[(r + 8) * PADW + kc];
                al[mi][2] = *(const uint32_t*)&Xl[(r    ) * PADW + kc + 8];
                al[mi][3] = *(const uint32_t*)&Xl[(r + 8) * PADW + kc + 8];
            }
            #pragma unroll
            for (int ni = 0; ni < 8; ni++) {
                const int n = warpN * 64 + ni * 8 + gp;
                uint32_t b[2], bl[2];
                b[0]  = *(const uint32_t*)&Wh[n * PADW + kc];
                b[1]  = *(const uint32_t*)&Wh[n * PADW + kc + 8];
                bl[0] = *(const uint32_t*)&Wl[n * PADW + kc];
                bl[1] = *(const uint32_t*)&Wl[n * PADW + kc + 8];
                #pragma unroll
                for (int mi = 0; mi < 2; mi++) {
                    mma16816(acc[mi][ni], a[mi], b);
                    mma16816(acc[mi][ni], a[mi], bl);
                    mma16816(acc[mi][ni], al[mi], b);
                }
            }
        }
        __syncthreads();
    }

    const int b  = m0 >> 11;
    const int s0 = m0 & (NS - 1);

    float* Vst = (float*)smraw;    // [128][131] staging (67072 B < smem)
    #pragma unroll
    for (int mi = 0; mi < 2; mi++)
        #pragma unroll
        for (int ni = 0; ni < 8; ni++) {
            const int r = warpM * 32 + mi * 16 + gp;
            const int cn = warpN * 64 + ni * 8 + tig * 2;
            const float bx = bv[hp * 128 + cn], by = bv[hp * 128 + cn + 1];
            #pragma unroll
            for (int half = 0; half < 2; half++) {
                const int rr = r + half * 8;
                Vst[rr * 131 + cn    ] = acc[mi][ni][2*half+0] + bx;
                Vst[rr * 131 + cn + 1] = acc[mi][ni][2*half+1] + by;
            }
        }
    __syncthreads();
    // coalesced fp32 V (2 heads)
    #pragma unroll
    for (int i = 0; i < 16; i++) {
        int u = tid + i * 256;
        int r = u >> 5, c4 = (u & 31) * 4;
        int head = hp * 2 + (c4 >> 6), d = c4 & 63;
        float4 w = make_float4(Vst[r*131+c4], Vst[r*131+c4+1], Vst[r*131+c4+2], Vst[r*131+c4+3]);
        *(float4*)&g_v[((size_t)(b * NH + head) * NS + s0 + r) * ND + d] = w;
    }
    // coalesced transposed bf16 V
    const int t0 = s0 >> 6;
    #pragma unroll
    for (int i = 0; i < 32; i++) {
        int u = tid + i * 256;
        int j = (u & 31) * 2, cc = (u >> 5) & 127, tl = u >> 12;
        int head = hp * 2 + (cc >> 6), d = cc & 63;
        uint32_t p = pack_bf16x2(Vst[(tl*64 + j)*131 + cc], Vst[(tl*64 + j + 1)*131 + cc]);
        *(uint32_t*)&g_vtb[(((size_t)(b * NH + head) * NT + t0 + tl) * ND + d) * 64 + j] = p;
    }
}

// ---------------------------------------------------------------------------
// Kernels 2a/2b/2c: parallel per-row exclusive suffix sums (register-buffered).
// ---------------------------------------------------------------------------
__global__ void tile_sum_kernel()
{
    const int bh = blockIdx.x, t = blockIdx.y, d = threadIdx.x;
    const float* v = g_v + ((size_t)bh * NS + t * 64) * ND + d;
    float vals[64];
    #pragma unroll
    for (int j = 0; j < 64; j++) vals[j] = v[(size_t)j * ND];
    float a = 0.f;
    #pragma unroll
    for (int j = 0; j < 64; j++) a += vals[j];
    g_tsum[((size_t)bh * NT + t) * ND + d] = a;
}
__global__ void tile_suffix_kernel()
{
    const int bh = blockIdx.x, d = threadIdx.x;
    float vals[NT];
    #pragma unroll
    for (int t = 0; t < NT; t++) vals[t] = g_tsum[((size_t)bh * NT + t) * ND + d];
    float acc = 0.f;
    #pragma unroll
    for (int t = NT - 1; t >= 0; t--) {
        g_tsuf[((size_t)bh * NT + t) * ND + d] = acc;
        acc += vals[t];
    }
    g_vt[bh * ND + d] = acc;
}
__global__ void row_suffix_kernel()
{
    const int bh = blockIdx.x, t = blockIdx.y, d = threadIdx.x;
    const float* v = g_v + ((size_t)bh * NS + t * 64) * ND + d;
    float vals[64];
    #pragma unroll
    for (int j = 0; j < 64; j++) vals[j] = v[(size_t)j * ND];
    float acc = g_tsuf[((size_t)bh * NT + t) * ND + d];
    float* sx = g_sufx + ((size_t)bh * NS + t * 64) * ND + d;
    #pragma unroll
    for (int j = 63; j >= 0; j--) {
        sx[(size_t)j * ND] = acc;
        acc += vals[j];
    }
}

// ---------------------------------------------------------------------------
// Kernel 3: register-resident flash attention, 3-stage cp.async pipeline,
// ldmatrix.x4 fragment loads.  (R13 structure, unchanged.)
// ---------------------------------------------------------------------------
__global__ __launch_bounds__(256, 2) void attn_mma(
    const float* __restrict__ pos_bias, float* __restrict__ out)
{
    extern __shared__ __align__(16) char smr[];
    __nv_bfloat16* Qb  = (__nv_bfloat16*)smr;        // [64][72]
    __nv_bfloat16* KV0 = Qb + 64 * PADW;             // 3 slots x (K,V), each 64*PADW
    float* posw  = (float*)(KV0 + 6 * KVBUF);        // [3][128]
    float* pm    = posw + 384;                       // [64][2]
    float* pl    = pm + 128;                         // [64][2]
    float* lse_s = pl + 128;                         // [64]
    float* Obuf  = (float*)smr;                      // overlay [64][66]

    const int tq = NT - 1 - blockIdx.x;              // heavy blocks first
    const int h  = blockIdx.y;
    const int b  = blockIdx.z;
    const int bh = b * NH + h;
    const int q0 = tq * 64;
    const int tid = threadIdx.x;
    const int wid = tid >> 5, lane = tid & 31;
    const int warpM = wid >> 1, warpN = wid & 1;
    const int gp = lane >> 2, tig = lane & 3;
    const int rbase = warpM * 16 + gp;

    // ldmatrix lane-relative offsets (loop-invariant, bytes)
    const int mrow = (lane & 7) | ((lane >> 4) << 3);
    const int ksub = (lane >> 3) & 1;
    uint32_t qk_off[2], sv_off[4];
    #pragma unroll
    for (int g = 0; g < 2; g++)
        qk_off[g] = ((warpN * 32 + g * 16 + mrow) * PADW + ksub * 8) * 2;
    #pragma unroll
    for (int g2 = 0; g2 < 4; g2++)
        sv_off[g2] = ((g2 * 16 + mrow) * PADW + warpN * 32 + ksub * 8) * 2;

    auto prefetch = [&](int t, int s) {
        const int k0 = t * 64;
        __nv_bfloat16* Ks = KV0 + s * 2 * KVBUF;
        __nv_bfloat16* Vs = Ks + KVBUF;
        #pragma unroll
        for (int j = 0; j < 2; j++) {
            int u = tid + j * 256;
            int r = u >> 3, cg = (u & 7) * 8;
            cpa16(s2u(&Ks[r * PADW + cg]), g_kb + ((size_t)bh * NS + k0 + r) * ND + cg);
            cpa16(s2u(&Vs[r * PADW + cg]), g_vtb + (((size_t)bh * NT + t) * ND + r) * 64 + cg);
        }
        if (tid < 128) {
            int idx = q0 - k0 - 63 + tid + NS - 1;
            if (idx <= 2 * NS - 2)
                cpa4(s2u(&posw[s * 128 + tid]), &pos_bias[(size_t)h * (2 * NS - 1) + idx]);
            else
                posw[s * 128 + tid] = 0.f;
        }
    };

    prefetch(0, 0); CP_COMMIT();
    if (tq >= 1) prefetch(1, 1);
    CP_COMMIT();

    #pragma unroll
    for (int j = 0; j < 2; j++) {
        int u = tid + j * 256;
        int r = u >> 3, cg = (u & 7) * 8;
        *(uint4*)&Qb[r * PADW + cg] = *(const uint4*)(g_qb + ((size_t)bh * NS + q0 + r) * ND + cg);
    }
    __syncthreads();
    uint32_t aq[4][4];
    #pragma unroll
    for (int ks = 0; ks < 4; ks++) {
        const int kc = ks * 16 + tig * 2;
        aq[ks][0] = *(const uint32_t*)&Qb[(rbase    ) * PADW + kc];
        aq[ks][1] = *(const uint32_t*)&Qb[(rbase + 8) * PADW + kc];
        aq[ks][2] = *(const uint32_t*)&Qb[(rbase    ) * PADW + kc + 8];
        aq[ks][3] = *(const uint32_t*)&Qb[(rbase + 8) * PADW + kc + 8];
    }

    float oacc[8][4] = {};
    float m0r = NEGM, l0r = 0.f, m1r = NEGM, l1r = 0.f;

    for (int t = 0; t <= tq; t++) {
        const bool diag = (t == tq);
        const int s = t % 3;
        CP_WAIT1();
        __syncthreads();
        if (t + 2 <= tq) prefetch(t + 2, (t + 2) % 3);
        CP_COMMIT();

        const __nv_bfloat16* Ks = KV0 + s * 2 * KVBUF;
        const __nv_bfloat16* Vs = Ks + KVBUF;
        const float* pw = posw + s * 128;
        const uint32_t ksaddr = s2u(Ks);
        const uint32_t vsaddr = s2u(Vs);

        float cS[4][4] = {};
        #pragma unroll
        for (int ks = 0; ks < 4; ks++) {
            uint32_t bb[4][2];
            #pragma unroll
            for (int g = 0; g < 2; g++)
                ldsm4(bb[g*2][0], bb[g*2][1], bb[g*2+1][0], bb[g*2+1][1],
                      ksaddr + qk_off[g] + ks * 32);
            #pragma unroll
            for (int ni = 0; ni < 4; ni++) mma16816(cS[ni], aq[ks], bb[ni]);
        }

        float e0[8], e1[8];
        uint32_t sf[2][4];
        #pragma unroll
        for (int ni = 0; ni < 4; ni++) {
            const int kcol = warpN * 32 + ni * 8 + tig * 2;
            float v00 = cS[ni][0] + pw[rbase     - kcol + 63];
            float v01 = cS[ni][1] + pw[rbase     - kcol + 62];
            float v10 = cS[ni][2] + pw[rbase + 8 - kcol + 63];
            float v11 = cS[ni][3] + pw[rbase + 8 - kcol + 62];
            float p00 = v00, p01 = v01, p10 = v10, p11 = v11;
            if (diag) {
                if (kcol     > rbase)     { v00 = NEGM; p00 = 0.f; }
                if (kcol + 1 > rbase)     { v01 = NEGM; p01 = 0.f; }
                if (kcol     > rbase + 8) { v10 = NEGM; p10 = 0.f; }
                if (kcol + 1 > rbase + 8) { v11 = NEGM; p11 = 0.f; }
            }
            e0[ni*2] = v00; e0[ni*2+1] = v01;
            e1[ni*2] = v10; e1[ni*2+1] = v11;
            const int ks2 = ni >> 1;
            if ((ni & 1) == 0) {
                sf[ks2][0] = pack_bf16x2(p00, p01);
                sf[ks2][1] = pack_bf16x2(p10, p11);
            } else {
                sf[ks2][2] = pack_bf16x2(p00, p01);
                sf[ks2][3] = pack_bf16x2(p10, p11);
            }
        }
        {
            float vm = e0[0];
            #pragma unroll
            for (int j = 1; j < 8; j++) vm = fmaxf(vm, e0[j]);
            float mn = fmaxf(m0r, vm);
            float sum = 0.f;
            #pragma unroll
            for (int j = 0; j < 8; j++) sum += __expf(e0[j] - mn);
            l0r = l0r * __expf(m0r - mn) + sum; m0r = mn;
        }
        {
            float vm = e1[0];
            #pragma unroll
            for (int j = 1; j < 8; j++) vm = fmaxf(vm, e1[j]);
            float mn = fmaxf(m1r, vm);
            float sum = 0.f;
            #pragma unroll
            for (int j = 0; j < 8; j++) sum += __expf(e1[j] - mn);
            l1r = l1r * __expf(m1r - mn) + sum; m1r = mn;
        }

        #pragma unroll
        for (int ks2 = 0; ks2 < 2; ks2++) {
            #pragma unroll
            for (int g2 = 0; g2 < 4; g2++) {
                uint32_t t0, t1, t2, t3;
                ldsm4(t0, t1, t2, t3, vsaddr + sv_off[g2] + ks2 * 32);
                uint32_t ba[2] = {t0, t1}, bc[2] = {t2, t3};
                mma16816(oacc[g2*2    ], sf[ks2], ba);
                mma16816(oacc[g2*2 + 1], sf[ks2], bc);
            }
        }
    }

    CP_WAIT0();
    __syncthreads();
    #pragma unroll
    for (int d = 1; d < 4; d <<= 1) {
        float mo = __shfl_xor_sync(0xffffffffu, m0r, d);
        float lo = __shfl_xor_sync(0xffffffffu, l0r, d);
        float mn = fmaxf(m0r, mo);
        l0r = l0r * __expf(m0r - mn) + lo * __expf(mo - mn); m0r = mn;
        mo = __shfl_xor_sync(0xffffffffu, m1r, d);
        lo = __shfl_xor_sync(0xffffffffu, l1r, d);
        mn = fmaxf(m1r, mo);
        l1r = l1r * __expf(m1r - mn) + lo * __expf(mo - mn); m1r = mn;
    }
    if (tig == 0) {
        pm[rbase * 2 + warpN] = m0r;       pl[rbase * 2 + warpN] = l0r;
        pm[(rbase + 8) * 2 + warpN] = m1r; pl[(rbase + 8) * 2 + warpN] = l1r;
    }
    __syncthreads();
    if (tid < 64) {
        float ma = pm[tid*2], mb_ = pm[tid*2+1], la = pl[tid*2], lb = pl[tid*2+1];
        float mn = fmaxf(ma, mb_);
        lse_s[tid] = mn + logf(la * __expf(ma - mn) + lb * __expf(mb_ - mn));
    }
    __syncthreads();
    if (warpN == 1) {
        #pragma unroll
        for (int ni = 0; ni < 8; ni++) {
            const int d = ni * 8 + tig * 2;
            Obuf[rbase * 66 + d]           = oacc[ni][0];
            Obuf[rbase * 66 + d + 1]       = oacc[ni][1];
            Obuf[(rbase + 8) * 66 + d]     = oacc[ni][2];
            Obuf[(rbase + 8) * 66 + d + 1] = oacc[ni][3];
        }
    }
    __syncthreads();
    if (warpN == 0) {
        const float lse0 = lse_s[rbase], lse1 = lse_s[rbase + 8];
        const int q0r = q0 + rbase;
        #pragma unroll
        for (int ni = 0; ni < 8; ni++) {
            const int d = ni * 8 + tig * 2;
            float2 vt2 = *(const float2*)&g_vt[bh * ND + d];
            float2 sx0 = *(const float2*)&g_sufx[((size_t)bh * NS + q0r    ) * ND + d];
            float2 sx1 = *(const float2*)&g_sufx[((size_t)bh * NS + q0r + 8) * ND + d];
            float2 o0, o1;
            o0.x = oacc[ni][0] + Obuf[rbase * 66 + d]     + NEGV * sx0.x - lse0 * vt2.x;
            o0.y = oacc[ni][1] + Obuf[rbase * 66 + d + 1] + NEGV * sx0.y - lse0 * vt2.y;
            o1.x = oacc[ni][2] + Obuf[(rbase+8) * 66 + d]     + NEGV * sx1.x - lse1 * vt2.x;
            o1.y = oacc[ni][3] + Obuf[(rbase+8) * 66 + d + 1] + NEGV * sx1.y - lse1 * vt2.y;
            *(float2*)&out[(((size_t)b * NS + q0r    ) * NH + h) * ND + d] = o0;
            *(float2*)&out[(((size_t)b * NS + q0r + 8) * NH + h) * ND + d] = o1;
        }
    }
}

// ---------------------------------------------------------------------------
extern "C" void kernel_launch(void* const* d_in, const int* in_sizes, int n_in,
                              void* d_out, int out_size)
{
    (void)in_sizes; (void)n_in; (void)out_size;
    const float* query = (const float*)d_in[0];
    const float* key_  = (const float*)d_in[1];
    const float* value = (const float*)d_in[2];
    const float* Wq    = (const float*)d_in[3];
    const float* bq    = (const float*)d_in[4];
    const float* Wk    = (const float*)d_in[5];
    const float* bk    = (const float*)d_in[6];
    const float* Wv    = (const float*)d_in[7];
    const float* bv    = (const float*)d_in[8];
    const float* pos   = (const float*)d_in[9];

    const int n4x = 4096 * 1024 / 4, n4w = 1024 * 1024 / 4;
    f2bf_kernel<<<n4x / 256, 256>>>((const float4*)query, 0, 0, n4x);
    f2bf_kernel<<<n4x / 256, 256>>>((const float4*)key_,  1, 0, n4x);
    f2bf_kernel<<<n4x / 256, 256>>>((const float4*)value, 2, 1, n4x);
    f2bf_kernel<<<n4w / 256, 256>>>((const float4*)Wq,    4, 0, n4w);
    f2bf_kernel<<<n4w / 256, 256>>>((const float4*)Wk,    5, 0, n4w);
    f2bf_kernel<<<n4w / 256, 256>>>((const float4*)Wv,    6, 1, n4w);

    const int QK_SMEM = 2 * 2 * TILE_B;                 // 73728 B
    const int V_SMEM  = 2 * 4 * TILE_B;                 // 147456 B
    cudaFuncSetAttribute(proj_qk, cudaFuncAttributeMaxDynamicSharedMemorySize, QK_SMEM);
    cudaFuncSetAttribute(proj_v,  cudaFuncAttributeMaxDynamicSharedMemorySize, V_SMEM);
    proj_qk<<<dim3(8, 32, 2), 256, QK_SMEM>>>(bq, bk);
    proj_v<<<dim3(8, 32), 256, V_SMEM>>>(bv);

    tile_sum_kernel<<<dim3(NB * NH, NT), 64>>>();
    tile_suffix_kernel<<<dim3(NB * NH), 64>>>();
    row_suffix_kernel<<<dim3(NB * NH, NT), 64>>>();

    const int ATTN_SMEM = 64*PADW*2 + 6*KVBUF*2 + (384 + 128 + 128 + 64) * 4;  // 67328 B
    cudaFuncSetAttribute(attn_mma, cudaFuncAttributeMaxDynamicSharedMemorySize, ATTN_SMEM);
    attn_mma<<<dim3(NT, NH, NB), 256, ATTN_SMEM>>>(pos, (float*)d_out);
}

// round 15
// speedup vs baseline: 1.8592x; 1.5163x over previous
#include <cuda_runtime.h>
#include <cuda_bf16.h>
#include <math.h>
#include <stdint.h>

#define NB 2
#define NS 2048
#define NE 1024
#define NH 16
#define ND 64
#define NT 32            // NS / 64 key tiles
#define NEGV (-1e9f)
#define NEGM (-1e30f)
#define QSCALE 0.125f    // 1/sqrt(64)
#define PADW 72          // bf16 elements per smem row
#define KVBUF (64 * PADW)
#define TILE_B (128 * PADW * 2)   // 18432 B: one 128x64 bf16 tile in smem

// Scratch (allocation-free rule: __device__ globals)
__device__ float g_v[NB*NH*NS*ND];              // fp32 projected V (exact path)
__device__ float g_sufx[NB*NH*NS*ND];           // per-row exclusive suffix: sum_{k>s} v[k][d]
__device__ float g_vt[NB*NH*ND];                // total sum_k v[k][d]
__device__ float g_tsum[NB*NH*NT*ND];           // per-tile V sums
__device__ float g_tsuf[NB*NH*NT*ND];           // exclusive tile-level suffix
__device__ __nv_bfloat16 g_qb[NB*NH*NS*ND];     // bf16 Q (pre-scaled by 1/8)
__device__ __nv_bfloat16 g_kb[NB*NH*NS*ND];     // bf16 K
__device__ __nv_bfloat16 g_vtb[NB*NH*NS*ND];    // bf16 V transposed per 64-tile: [bh][t][d][64]
// bf16 slices: x: 0=query 1=key 2=value_hi 3=value_lo ; w: 0=Wq 1=Wk 2=Wv_hi 3=Wv_lo
__device__ __nv_bfloat16 g_xb[4u*4096*1024];
__device__ __nv_bfloat16 g_wb[4u*1024*1024];

// ---------------------------------------------------------------------------
__device__ __forceinline__ void mma16816(float* c, const uint32_t* a, const uint32_t* b) {
    asm volatile("mma.sync.aligned.m16n8k16.row.col.f32.bf16.bf16.f32 "
        "{%0,%1,%2,%3}, {%4,%5,%6,%7}, {%8,%9}, {%0,%1,%2,%3};"
        : "+f"(c[0]), "+f"(c[1]), "+f"(c[2]), "+f"(c[3])
        : "r"(a[0]), "r"(a[1]), "r"(a[2]), "r"(a[3]), "r"(b[0]), "r"(b[1]));
}
__device__ __forceinline__ void ldsm4(uint32_t& r0, uint32_t& r1, uint32_t& r2, uint32_t& r3,
                                      uint32_t addr) {
    asm volatile("ldmatrix.sync.aligned.m8n8.x4.shared.b16 {%0,%1,%2,%3}, [%4];"
        : "=r"(r0), "=r"(r1), "=r"(r2), "=r"(r3) : "r"(addr));
}
__device__ __forceinline__ uint32_t pack_bf16x2(float a, float b) {
    __nv_bfloat162 t = __floats2bfloat162_rn(a, b);
    return *(uint32_t*)&t;
}
__device__ __forceinline__ uint32_t s2u(const void* p) {
    uint32_t a;
    asm("{ .reg .u64 t; cvta.to.shared.u64 t, %1; cvt.u32.u64 %0, t; }" : "=r"(a) : "l"(p));
    return a;
}
__device__ __forceinline__ void cpa16(uint32_t d, const void* s) {
    asm volatile("cp.async.cg.shared.global [%0], [%1], 16;" :: "r"(d), "l"(s));
}
__device__ __forceinline__ void cpa4(uint32_t d, const void* s) {
    asm volatile("cp.async.ca.shared.global [%0], [%1], 4;" :: "r"(d), "l"(s));
}
#define CP_COMMIT() asm volatile("cp.async.commit_group;" ::: "memory")
#define CP_WAIT1()  asm volatile("cp.async.wait_group 1;" ::: "memory")
#define CP_WAIT0()  asm volatile("cp.async.wait_group 0;" ::: "memory")

// ---------------------------------------------------------------------------
// Kernel 0a/0b: fp32 -> bf16 conversions, merged launches (grid.y = tensor).
// ---------------------------------------------------------------------------
__device__ __forceinline__ void conv_one(const float4* src, __nv_bfloat16* hi,
                                         __nv_bfloat16* lo, int i, int do_split)
{
    float4 v = src[i];
    __nv_bfloat16 h0 = __float2bfloat16(v.x), h1 = __float2bfloat16(v.y);
    __nv_bfloat16 h2 = __float2bfloat16(v.z), h3 = __float2bfloat16(v.w);
    __nv_bfloat162* dh = (__nv_bfloat162*)hi;
    dh[2*i]   = __nv_bfloat162(h0, h1);
    dh[2*i+1] = __nv_bfloat162(h2, h3);
    if (do_split) {
        __nv_bfloat162* dl = (__nv_bfloat162*)lo;
        dl[2*i]   = __nv_bfloat162(__float2bfloat16(v.x - __bfloat162float(h0)),
                                   __float2bfloat16(v.y - __bfloat162float(h1)));
        dl[2*i+1] = __nv_bfloat162(__float2bfloat16(v.z - __bfloat162float(h2)),
                                   __float2bfloat16(v.w - __bfloat162float(h3)));
    }
}
__global__ void f2bf_x(const float4* __restrict__ q, const float4* __restrict__ k,
                       const float4* __restrict__ v)
{
    const int z = blockIdx.y;
    const float4* src = (z == 0) ? q : (z == 1) ? k : v;
    int i = blockIdx.x * blockDim.x + threadIdx.x;
    conv_one(src, g_xb + (size_t)z * 4096 * 1024, g_xb + (size_t)3 * 4096 * 1024, i, z == 2);
}
__global__ void f2bf_w(const float4* __restrict__ wq, const float4* __restrict__ wk,
                       const float4* __restrict__ wv)
{
    const int z = blockIdx.y;
    const float4* src = (z == 0) ? wq : (z == 1) ? wk : wv;
    int i = blockIdx.x * blockDim.x + threadIdx.x;
    conv_one(src, g_wb + (size_t)z * 1024 * 1024, g_wb + (size_t)3 * 1024 * 1024, i, z == 2);
}

// ---------------------------------------------------------------------------
// Kernel 1a: Q/K projections, 2-stage cp.async double-buffered.
// ---------------------------------------------------------------------------
__global__ __launch_bounds__(256) void proj_qk(
    const float* __restrict__ bq, const float* __restrict__ bk)
{
    extern __shared__ __align__(16) char smraw[];

    const int z = blockIdx.z;
    const __nv_bfloat16* Xg = g_xb + (size_t)z * 4096 * 1024;
    const __nv_bfloat16* Wg = g_wb + (size_t)z * 1024 * 1024;
    const float* bias = z ? bk : bq;

    const int hp = blockIdx.x;
    const int m0 = blockIdx.y * 128;
    const int tid = threadIdx.x;
    const int wid = tid >> 5, lane = tid & 31;
    const int warpM = wid >> 1, warpN = wid & 1;
    const int gp = lane >> 2, tig = lane & 3;

    auto prefetch = [&](int c) {
        const int st = c & 1;
        __nv_bfloat16* Xh = (__nv_bfloat16*)(smraw + st * 2 * TILE_B);
        __nv_bfloat16* Wh = Xh + 128 * PADW;
        const int k0 = c * 64;
        #pragma unroll
        for (int j = 0; j < 4; j++) {
            int u = tid + j * 256;
            int r = u >> 3, cg = (u & 7) * 8;
            cpa16(s2u(&Xh[r * PADW + cg]), Xg + (size_t)(m0 + r) * NE + k0 + cg);
            cpa16(s2u(&Wh[r * PADW + cg]), Wg + (size_t)(hp * 128 + r) * NE + k0 + cg);
        }
    };

    prefetch(0); CP_COMMIT();

    float acc[2][8][4] = {};

    for (int c = 0; c < 16; c++) {
        if (c < 15) { prefetch(c + 1); CP_COMMIT(); CP_WAIT1(); }
        else        { CP_WAIT0(); }
        __syncthreads();

        const int st = c & 1;
        const __nv_bfloat16* Xh = (const __nv_bfloat16*)(smraw + st * 2 * TILE_B);
        const __nv_bfloat16* Wh = Xh + 128 * PADW;

        #pragma unroll
        for (int ks = 0; ks < 4; ks++) {
            const int kc = ks * 16 + tig * 2;
            uint32_t a[2][4];
            #pragma unroll
            for (int mi = 0; mi < 2; mi++) {
                const int r = warpM * 32 + mi * 16 + gp;
                a[mi][0] = *(const uint32_t*)&Xh[(r    ) * PADW + kc];
                a[mi][1] = *(const uint32_t*)&Xh[(r + 8) * PADW + kc];
                a[mi][2] = *(const uint32_t*)&Xh[(r    ) * PADW + kc + 8];
                a[mi][3] = *(const uint32_t*)&Xh[(r + 8) * PADW + kc + 8];
            }
            #pragma unroll
            for (int ni = 0; ni < 8; ni++) {
                const int n = warpN * 64 + ni * 8 + gp;
                uint32_t b[2];
                b[0] = *(const uint32_t*)&Wh[n * PADW + kc];
                b[1] = *(const uint32_t*)&Wh[n * PADW + kc + 8];
                #pragma unroll
                for (int mi = 0; mi < 2; mi++) mma16816(acc[mi][ni], a[mi], b);
            }
        }
        __syncthreads();
    }

    const int b  = m0 >> 11;
    const int s0 = m0 & (NS - 1);
    const float sc = (z == 0) ? QSCALE : 1.0f;
    __nv_bfloat16* dst = (z == 0) ? g_qb : g_kb;
    const int head = hp * 2 + warpN;
    const size_t bh = (size_t)(b * NH + head);
    #pragma unroll
    for (int mi = 0; mi < 2; mi++)
        #pragma unroll
        for (int ni = 0; ni < 8; ni++) {
            const int r = warpM * 32 + mi * 16 + gp;
            const int d = ni * 8 + tig * 2;
            const float bx = bias[head * 64 + d], by = bias[head * 64 + d + 1];
            #pragma unroll
            for (int half = 0; half < 2; half++) {
                const int s = s0 + r + half * 8;
                float v0 = (acc[mi][ni][2*half+0] + bx) * sc;
                float v1 = (acc[mi][ni][2*half+1] + by) * sc;
                *(uint32_t*)&dst[(bh * NS + s) * ND + d] = pack_bf16x2(v0, v1);
            }
        }
}

// ---------------------------------------------------------------------------
// Kernel 1b: V projection (3-mma split-precision), 2-stage cp.async pipeline.
// ---------------------------------------------------------------------------
__global__ __launch_bounds__(256) void proj_v(const float* __restrict__ bv)
{
    extern __shared__ __align__(16) char smraw[];

    const __nv_bfloat16* Xg  = g_xb + (size_t)2 * 4096 * 1024;
    const __nv_bfloat16* Wg  = g_wb + (size_t)2 * 1024 * 1024;
    const __nv_bfloat16* XgL = g_xb + (size_t)3 * 4096 * 1024;
    const __nv_bfloat16* WgL = g_wb + (size_t)3 * 1024 * 1024;

    const int hp = blockIdx.x;
    const int m0 = blockIdx.y * 128;
    const int tid = threadIdx.x;
    const int wid = tid >> 5, lane = tid & 31;
    const int warpM = wid >> 1, warpN = wid & 1;
    const int gp = lane >> 2, tig = lane & 3;

    auto prefetch = [&](int c) {
        const int st = c & 1;
        __nv_bfloat16* Xh = (__nv_bfloat16*)(smraw + st * 4 * TILE_B);
        __nv_bfloat16* Wh = Xh + 128 * PADW;
        __nv_bfloat16* Xl = Wh + 128 * PADW;
        __nv_bfloat16* Wl = Xl + 128 * PADW;
        const int k0 = c * 64;
        #pragma unroll
        for (int j = 0; j < 4; j++) {
            int u = tid + j * 256;
            int r = u >> 3, cg = (u & 7) * 8;
            cpa16(s2u(&Xh[r * PADW + cg]), Xg  + (size_t)(m0 + r) * NE + k0 + cg);
            cpa16(s2u(&Wh[r * PADW + cg]), Wg  + (size_t)(hp * 128 + r) * NE + k0 + cg);
            cpa16(s2u(&Xl[r * PADW + cg]), XgL + (size_t)(m0 + r) * NE + k0 + cg);
            cpa16(s2u(&Wl[r * PADW + cg]), WgL + (size_t)(hp * 128 + r) * NE + k0 + cg);
        }
    };

    prefetch(0); CP_COMMIT();

    float acc[2][8][4] = {};

    for (int c = 0; c < 16; c++) {
        if (c < 15) { prefetch(c + 1); CP_COMMIT(); CP_WAIT1(); }
        else        { CP_WAIT0(); }
        __syncthreads();

        const int st = c & 1;
        const __nv_bfloat16* Xh = (const __nv_bfloat16*)(smraw + st * 4 * TILE_B);
        const __nv_bfloat16* Wh = Xh + 128 * PADW;
        const __nv_bfloat16* Xl = Wh + 128 * PADW;
        const __nv_bfloat16* Wl = Xl + 128 * PADW;

        #pragma unroll
        for (int ks = 0; ks < 4; ks++) {
            const int kc = ks * 16 + tig * 2;
            uint32_t a[2][4], al[2][4];
            #pragma unroll
            for (int mi = 0; mi < 2; mi++) {
                const int r = warpM * 32 + mi * 16 + gp;
                a[mi][0] = *(const uint32_t*)&Xh[(r    ) * PADW + kc];
                a[mi][1] = *(const uint32_t*)&Xh[(r + 8) * PADW + kc];
                a[mi][2] = *(const uint32_t*)&Xh[(r    ) * PADW + kc + 8];
                a[mi][3] = *(const uint32_t*)&Xh[(r + 8) * PADW + kc + 8];
                al[mi][0] = *(const uint32_t*)&Xl[(r    ) * PADW + kc];
                al[mi][1] = *(const uint32_t*)&Xl[(r + 8) * PADW + kc];
                al[mi][2] = *(const uint32_t*)&Xl[(r    ) * PADW + kc + 8];
                al[mi][3] = *(const uint32_t*)&Xl[(r + 8) * PADW + kc + 8];
            }
            #pragma unroll
            for (int ni = 0; ni < 8; ni++) {
                const int n = warpN * 64 + ni * 8 + gp;
                uint32_t b[2], bl[2];
                b[0]  = *(const uint32_t*)&Wh[n * PADW + kc];
                b[1]  = *(const uint32_t*)&Wh[n * PADW + kc + 8];
                bl[0] = *(const uint32_t*)&Wl[n * PADW + kc];
                bl[1] = *(const uint32_t*)&Wl[n * PADW + kc + 8];
                #pragma unroll
                for (int mi = 0; mi < 2; mi++) {
                    mma16816(acc[mi][ni], a[mi], b);
                    mma16816(acc[mi][ni], a[mi], bl);
                    mma16816(acc[mi][ni], al[mi], b);
                }
            }
        }
        __syncthreads();
    }

    const int b  = m0 >> 11;
    const int s0 = m0 & (NS - 1);

    float* Vst = (float*)smraw;    // [128][131] staging
    #pragma unroll
    for (int mi = 0; mi < 2; mi++)
        #pragma unroll
        for (int ni = 0; ni < 8; ni++) {
            const int r = warpM * 32 + mi * 16 + gp;
            const int cn = warpN * 64 + ni * 8 + tig * 2;
            const float bx = bv[hp * 128 + cn], by = bv[hp * 128 + cn + 1];
            #pragma unroll
            for (int half = 0; half < 2; half++) {
                const int rr = r + half * 8;
                Vst[rr * 131 + cn    ] = acc[mi][ni][2*half+0] + bx;
                Vst[rr * 131 + cn + 1] = acc[mi][ni][2*half+1] + by;
            }
        }
    __syncthreads();
    #pragma unroll
    for (int i = 0; i < 16; i++) {
        int u = tid + i * 256;
        int r = u >> 5, c4 = (u & 31) * 4;
        int head = hp * 2 + (c4 >> 6), d = c4 & 63;
        float4 w = make_float4(Vst[r*131+c4], Vst[r*131+c4+1], Vst[r*131+c4+2], Vst[r*131+c4+3]);
        *(float4*)&g_v[((size_t)(b * NH + head) * NS + s0 + r) * ND + d] = w;
    }
    const int t0 = s0 >> 6;
    #pragma unroll
    for (int i = 0; i < 32; i++) {
        int u = tid + i * 256;
        int j = (u & 31) * 2, cc = (u >> 5) & 127, tl = u >> 12;
        int head = hp * 2 + (cc >> 6), d = cc & 63;
        uint32_t p = pack_bf16x2(Vst[(tl*64 + j)*131 + cc], Vst[(tl*64 + j + 1)*131 + cc]);
        *(uint32_t*)&g_vtb[(((size_t)(b * NH + head) * NT + t0 + tl) * ND + d) * 64 + j] = p;
    }
}

// ---------------------------------------------------------------------------
// Kernels 2a/2b/2c: parallel per-row exclusive suffix sums (register-buffered).
// ---------------------------------------------------------------------------
__global__ void tile_sum_kernel()
{
    const int bh = blockIdx.x, t = blockIdx.y, d = threadIdx.x;
    const float* v = g_v + ((size_t)bh * NS + t * 64) * ND + d;
    float vals[64];
    #pragma unroll
    for (int j = 0; j < 64; j++) vals[j] = v[(size_t)j * ND];
    float a = 0.f;
    #pragma unroll
    for (int j = 0; j < 64; j++) a += vals[j];
    g_tsum[((size_t)bh * NT + t) * ND + d] = a;
}
__global__ void tile_suffix_kernel()
{
    const int bh = blockIdx.x, d = threadIdx.x;
    float vals[NT];
    #pragma unroll
    for (int t = 0; t < NT; t++) vals[t] = g_tsum[((size_t)bh * NT + t) * ND + d];
    float acc = 0.f;
    #pragma unroll
    for (int t = NT - 1; t >= 0; t--) {
        g_tsuf[((size_t)bh * NT + t) * ND + d] = acc;
        acc += vals[t];
    }
    g_vt[bh * ND + d] = acc;
}
__global__ void row_suffix_kernel()
{
    const int bh = blockIdx.x, t = blockIdx.y, d = threadIdx.x;
    const float* v = g_v + ((size_t)bh * NS + t * 64) * ND + d;
    float vals[64];
    #pragma unroll
    for (int j = 0; j < 64; j++) vals[j] = v[(size_t)j * ND];
    float acc = g_tsuf[((size_t)bh * NT + t) * ND + d];
    float* sx = g_sufx + ((size_t)bh * NS + t * 64) * ND + d;
    #pragma unroll
    for (int j = 63; j >= 0; j--) {
        sx[(size_t)j * ND] = acc;
        acc += vals[j];
    }
}

// ---------------------------------------------------------------------------
// Kernel 3: register-resident flash attention; 4-slot cp.async pipeline,
// pair-processed mainloop (one wait per 2 tiles), ldmatrix fragment loads.
// ---------------------------------------------------------------------------
__global__ __launch_bounds__(256, 2) void attn_mma(
    const float* __restrict__ pos_bias, float* __restrict__ out)
{
    extern __shared__ __align__(16) char smr[];
    __nv_bfloat16* Qb  = (__nv_bfloat16*)smr;        // [64][72]
    __nv_bfloat16* KV0 = Qb + 64 * PADW;             // 4 slots x (K,V), each 64*PADW
    float* posw  = (float*)(KV0 + 8 * KVBUF);        // [4][128]
    float* pm    = posw + 512;                       // [64][2]
    float* pl    = pm + 128;                         // [64][2]
    float* lse_s = pl + 128;                         // [64]
    float* Obuf  = (float*)smr;                      // overlay [64][66]

    const int tq = NT - 1 - blockIdx.x;              // heavy blocks first
    const int h  = blockIdx.y;
    const int b  = blockIdx.z;
    const int bh = b * NH + h;
    const int q0 = tq * 64;
    const int tid = threadIdx.x;
    const int wid = tid >> 5, lane = tid & 31;
    const int warpM = wid >> 1, warpN = wid & 1;
    const int gp = lane >> 2, tig = lane & 3;
    const int rbase = warpM * 16 + gp;

    // ldmatrix lane-relative offsets (loop-invariant, bytes)
    const int mrow = (lane & 7) | ((lane >> 4) << 3);
    const int ksub = (lane >> 3) & 1;
    uint32_t qk_off[2], sv_off[4];
    #pragma unroll
    for (int g = 0; g < 2; g++)
        qk_off[g] = ((warpN * 32 + g * 16 + mrow) * PADW + ksub * 8) * 2;
    #pragma unroll
    for (int g2 = 0; g2 < 4; g2++)
        sv_off[g2] = ((g2 * 16 + mrow) * PADW + warpN * 32 + ksub * 8) * 2;

    auto prefetch = [&](int t) {
        const int s = t & 3;
        const int k0 = t * 64;
        __nv_bfloat16* Ks = KV0 + s * 2 * KVBUF;
        __nv_bfloat16* Vs = Ks + KVBUF;
        #pragma unroll
        for (int j = 0; j < 2; j++) {
            int u = tid + j * 256;
            int r = u >> 3, cg = (u & 7) * 8;
            cpa16(s2u(&Ks[r * PADW + cg]), g_kb + ((size_t)bh * NS + k0 + r) * ND + cg);
            cpa16(s2u(&Vs[r * PADW + cg]), g_vtb + (((size_t)bh * NT + t) * ND + r) * 64 + cg);
        }
        if (tid < 128) {
            int idx = q0 - k0 - 63 + tid + NS - 1;
            if (idx <= 2 * NS - 2)
                cpa4(s2u(&posw[s * 128 + tid]), &pos_bias[(size_t)h * (2 * NS - 1) + idx]);
            else
                posw[s * 128 + tid] = 0.f;
        }
    };

    prefetch(0);
    if (tq >= 1) prefetch(1);
    CP_COMMIT();
    if (tq >= 2) prefetch(2);
    if (tq >= 3) prefetch(3);
    CP_COMMIT();

    // Q tile -> smem -> fragments (resident all tiles)
    #pragma unroll
    for (int j = 0; j < 2; j++) {
        int u = tid + j * 256;
        int r = u >> 3, cg = (u & 7) * 8;
        *(uint4*)&Qb[r * PADW + cg] = *(const uint4*)(g_qb + ((size_t)bh * NS + q0 + r) * ND + cg);
    }
    __syncthreads();
    uint32_t aq[4][4];
    #pragma unroll
    for (int ks = 0; ks < 4; ks++) {
        const int kc = ks * 16 + tig * 2;
        aq[ks][0] = *(const uint32_t*)&Qb[(rbase    ) * PADW + kc];
        aq[ks][1] = *(const uint32_t*)&Qb[(rbase + 8) * PADW + kc];
        aq[ks][2] = *(const uint32_t*)&Qb[(rbase    ) * PADW + kc + 8];
        aq[ks][3] = *(const uint32_t*)&Qb[(rbase + 8) * PADW + kc + 8];
    }

    float oacc[8][4] = {};
    float m0r = NEGM, l0r = 0.f, m1r = NEGM, l1r = 0.f;

    auto compute_tile = [&](int t) {
        const bool diag = (t == tq);
        const int s = t & 3;
        const __nv_bfloat16* Ks = KV0 + s * 2 * KVBUF;
        const __nv_bfloat16* Vs = Ks + KVBUF;
        const float* pw = posw + s * 128;
        const uint32_t ksaddr = s2u(Ks);
        const uint32_t vsaddr = s2u(Vs);

        float cS[4][4] = {};
        #pragma unroll
        for (int ks = 0; ks < 4; ks++) {
            uint32_t bb[4][2];
            #pragma unroll
            for (int g = 0; g < 2; g++)
                ldsm4(bb[g*2][0], bb[g*2][1], bb[g*2+1][0], bb[g*2+1][1],
                      ksaddr + qk_off[g] + ks * 32);
            #pragma unroll
            for (int ni = 0; ni < 4; ni++) mma16816(cS[ni], aq[ks], bb[ni]);
        }

        float e0[8], e1[8];
        uint32_t sf[2][4];
        #pragma unroll
        for (int ni = 0; ni < 4; ni++) {
            const int kcol = warpN * 32 + ni * 8 + tig * 2;
            float v00 = cS[ni][0] + pw[rbase     - kcol + 63];
            float v01 = cS[ni][1] + pw[rbase     - kcol + 62];
            float v10 = cS[ni][2] + pw[rbase + 8 - kcol + 63];
            float v11 = cS[ni][3] + pw[rbase + 8 - kcol + 62];
            float p00 = v00, p01 = v01, p10 = v10, p11 = v11;
            if (diag) {
                if (kcol     > rbase)     { v00 = NEGM; p00 = 0.f; }
                if (kcol + 1 > rbase)     { v01 = NEGM; p01 = 0.f; }
                if (kcol     > rbase + 8) { v10 = NEGM; p10 = 0.f; }
                if (kcol + 1 > rbase + 8) { v11 = NEGM; p11 = 0.f; }
            }
            e0[ni*2] = v00; e0[ni*2+1] = v01;
            e1[ni*2] = v10; e1[ni*2+1] = v11;
            const int ks2 = ni >> 1;
            if ((ni & 1) == 0) {
                sf[ks2][0] = pack_bf16x2(p00, p01);
                sf[ks2][1] = pack_bf16x2(p10, p11);
            } else {
                sf[ks2][2] = pack_bf16x2(p00, p01);
                sf[ks2][3] = pack_bf16x2(p10, p11);
            }
        }
        {
            float vm = e0[0];
            #pragma unroll
            for (int j = 1; j < 8; j++) vm = fmaxf(vm, e0[j]);
            float mn = fmaxf(m0r, vm);
            float sum = 0.f;
            #pragma unroll
            for (int j = 0; j < 8; j++) sum += __expf(e0[j] - mn);
            l0r = l0r * __expf(m0r - mn) + sum; m0r = mn;
        }
        {
            float vm = e1[0];
            #pragma unroll
            for (int j = 1; j < 8; j++) vm = fmaxf(vm, e1[j]);
            float mn = fmaxf(m1r, vm);
            float sum = 0.f;
            #pragma unroll
            for (int j = 0; j < 8; j++) sum += __expf(e1[j] - mn);
            l1r = l1r * __expf(m1r - mn) + sum; m1r = mn;
        }

        #pragma unroll
        for (int ks2 = 0; ks2 < 2; ks2++) {
            #pragma unroll
            for (int g2 = 0; g2 < 4; g2++) {
                uint32_t t0r, t1r, t2r, t3r;
                ldsm4(t0r, t1r, t2r, t3r, vsaddr + sv_off[g2] + ks2 * 32);
                uint32_t ba[2] = {t0r, t1r}, bc[2] = {t2r, t3r};
                mma16816(oacc[g2*2    ], sf[ks2], ba);
                mma16816(oacc[g2*2 + 1], sf[ks2], bc);
            }
        }
    };

    for (int t0 = 0; t0 <= tq; t0 += 2) {
        CP_WAIT1();                 // pair (t0, t0+1) resident
        __syncthreads();
        compute_tile(t0);
        if (t0 + 1 <= tq) compute_tile(t0 + 1);
        __syncthreads();            // all warps done with slots t0&3, (t0+1)&3
        if (t0 + 4 <= tq) prefetch(t0 + 4);
        if (t0 + 5 <= tq) prefetch(t0 + 5);
        CP_COMMIT();                // always commit (keeps group counts aligned)
    }

    CP_WAIT0();
    __syncthreads();
    #pragma unroll
    for (int d = 1; d < 4; d <<= 1) {
        float mo = __shfl_xor_sync(0xffffffffu, m0r, d);
        float lo = __shfl_xor_sync(0xffffffffu, l0r, d);
        float mn = fmaxf(m0r, mo);
        l0r = l0r * __expf(m0r - mn) + lo * __expf(mo - mn); m0r = mn;
        mo = __shfl_xor_sync(0xffffffffu, m1r, d);
        lo = __shfl_xor_sync(0xffffffffu, l1r, d);
        mn = fmaxf(m1r, mo);
        l1r = l1r * __expf(m1r - mn) + lo * __expf(mo - mn); m1r = mn;
    }
    if (tig == 0) {
        pm[rbase * 2 + warpN] = m0r;       pl[rbase * 2 + warpN] = l0r;
        pm[(rbase + 8) * 2 + warpN] = m1r; pl[(rbase + 8) * 2 + warpN] = l1r;
    }
    __syncthreads();
    if (tid < 64) {
        float ma = pm[tid*2], mb_ = pm[tid*2+1], la = pl[tid*2], lb = pl[tid*2+1];
        float mn = fmaxf(ma, mb_);
        lse_s[tid] = mn + logf(la * __expf(ma - mn) + lb * __expf(mb_ - mn));
    }
    __syncthreads();
    if (warpN == 1) {
        #pragma unroll
        for (int ni = 0; ni < 8; ni++) {
            const int d = ni * 8 + tig * 2;
            Obuf[rbase * 66 + d]           = oacc[ni][0];
            Obuf[rbase * 66 + d + 1]       = oacc[ni][1];
            Obuf[(rbase + 8) * 66 + d]     = oacc[ni][2];
            Obuf[(rbase + 8) * 66 + d + 1] = oacc[ni][3];
        }
    }
    __syncthreads();
    if (warpN == 0) {
        const float lse0 = lse_s[rbase], lse1 = lse_s[rbase + 8];
        const int q0r = q0 + rbase;
        #pragma unroll
        for (int ni = 0; ni < 8; ni++) {
            const int d = ni * 8 + tig * 2;
            float2 vt2 = *(const float2*)&g_vt[bh * ND + d];
            float2 sx0 = *(const float2*)&g_sufx[((size_t)bh * NS + q0r    ) * ND + d];
            float2 sx1 = *(const float2*)&g_sufx[((size_t)bh * NS + q0r + 8) * ND + d];
            float2 o0, o1;
            o0.x = oacc[ni][0] + Obuf[rbase * 66 + d]     + NEGV * sx0.x - lse0 * vt2.x;
            o0.y = oacc[ni][1] + Obuf[rbase * 66 + d + 1] + NEGV * sx0.y - lse0 * vt2.y;
            o1.x = oacc[ni][2] + Obuf[(rbase+8) * 66 + d]     + NEGV * sx1.x - lse1 * vt2.x;
            o1.y = oacc[ni][3] + Obuf[(rbase+8) * 66 + d + 1] + NEGV * sx1.y - lse1 * vt2.y;
            *(float2*)&out[(((size_t)b * NS + q0r    ) * NH + h) * ND + d] = o0;
            *(float2*)&out[(((size_t)b * NS + q0r + 8) * NH + h) * ND + d] = o1;
        }
    }
}

// ---------------------------------------------------------------------------
extern "C" void kernel_launch(void* const* d_in, const int* in_sizes, int n_in,
                              void* d_out, int out_size)
{
    (void)in_sizes; (void)n_in; (void)out_size;
    const float* query = (const float*)d_in[0];
    const float* key_  = (const float*)d_in[1];
    const float* value = (const float*)d_in[2];
    const float* Wq    = (const float*)d_in[3];
    const float* bq    = (const float*)d_in[4];
    const float* Wk    = (const float*)d_in[5];
    const float* bk    = (const float*)d_in[6];
    const float* Wv    = (const float*)d_in[7];
    const float* bv    = (const float*)d_in[8];
    const float* pos   = (const float*)d_in[9];

    f2bf_x<<<dim3(4096, 3), 256>>>((const float4*)query, (const float4*)key_, (const float4*)value);
    f2bf_w<<<dim3(1024, 3), 256>>>((const float4*)Wq, (const float4*)Wk, (const float4*)Wv);

    const int QK_SMEM = 2 * 2 * TILE_B;                 // 73728 B
    const int V_SMEM  = 2 * 4 * TILE_B;                 // 147456 B
    cudaFuncSetAttribute(proj_qk, cudaFuncAttributeMaxDynamicSharedMemorySize, QK_SMEM);
    cudaFuncSetAttribute(proj_v,  cudaFuncAttributeMaxDynamicSharedMemorySize, V_SMEM);
    proj_qk<<<dim3(8, 32, 2), 256, QK_SMEM>>>(bq, bk);
    proj_v<<<dim3(8, 32), 256, V_SMEM>>>(bv);

    tile_sum_kernel<<<dim3(NB * NH, NT), 64>>>();
    tile_suffix_kernel<<<dim3(NB * NH), 64>>>();
    row_suffix_kernel<<<dim3(NB * NH, NT), 64>>>();

    // Qb + 4*(K,V) + posw[4][128] + pm/pl/lse
    const int ATTN_SMEM = 64*PADW*2 + 8*KVBUF*2 + (512 + 128 + 128 + 64) * 4;  // 86272 B
    cudaFuncSetAttribute(attn_mma, cudaFuncAttributeMaxDynamicSharedMemorySize, ATTN_SMEM);
    attn_mma<<<dim3(NT, NH, NB), 256, ATTN_SMEM>>>(pos, (float*)d_out);
}

// round 16
// speedup vs baseline: 1.8866x; 1.0147x over previous
#include <cuda_runtime.h>
#include <cuda_bf16.h>
#include <math.h>
#include <stdint.h>

#define NB 2
#define NS 2048
#define NE 1024
#define NH 16
#define ND 64
#define NT 32            // NS / 64 key tiles
#define NEGV (-1e9f)
#define NEGM (-1e30f)
#define QSCALE 0.125f    // 1/sqrt(64)
#define PADW 72          // bf16 elements per smem row
#define KVBUF (64 * PADW)
#define TILE_B (128 * PADW * 2)   // 18432 B: one 128x64 bf16 tile in smem

// Scratch (allocation-free rule: __device__ globals)
__device__ float g_v[NB*NH*NS*ND];              // fp32 projected V (exact path)
__device__ float g_sufx[NB*NH*NS*ND];           // per-row exclusive suffix: sum_{k>s} v[k][d]
__device__ float g_vt[NB*NH*ND];                // total sum_k v[k][d]
__device__ float g_tsum[NB*NH*NT*ND];           // per-tile V sums
__device__ float g_tsuf[NB*NH*NT*ND];           // exclusive tile-level suffix
__device__ __nv_bfloat16 g_qb[NB*NH*NS*ND];     // bf16 Q (pre-scaled by 1/8)
__device__ __nv_bfloat16 g_kb[NB*NH*NS*ND];     // bf16 K
__device__ __nv_bfloat16 g_vtb[NB*NH*NS*ND];    // bf16 V transposed per 64-tile: [bh][t][d][64]
// bf16 slices: x: 0=query 1=key 2=value_hi 3=value_lo ; w: 0=Wq 1=Wk 2=Wv_hi 3=Wv_lo
__device__ __nv_bfloat16 g_xb[4u*4096*1024];
__device__ __nv_bfloat16 g_wb[4u*1024*1024];

// ---------------------------------------------------------------------------
__device__ __forceinline__ void mma16816(float* c, const uint32_t* a, const uint32_t* b) {
    asm volatile("mma.sync.aligned.m16n8k16.row.col.f32.bf16.bf16.f32 "
        "{%0,%1,%2,%3}, {%4,%5,%6,%7}, {%8,%9}, {%0,%1,%2,%3};"
        : "+f"(c[0]), "+f"(c[1]), "+f"(c[2]), "+f"(c[3])
        : "r"(a[0]), "r"(a[1]), "r"(a[2]), "r"(a[3]), "r"(b[0]), "r"(b[1]));
}
__device__ __forceinline__ void ldsm4(uint32_t& r0, uint32_t& r1, uint32_t& r2, uint32_t& r3,
                                      uint32_t addr) {
    asm volatile("ldmatrix.sync.aligned.m8n8.x4.shared.b16 {%0,%1,%2,%3}, [%4];"
        : "=r"(r0), "=r"(r1), "=r"(r2), "=r"(r3) : "r"(addr));
}
__device__ __forceinline__ uint32_t pack_bf16x2(float a, float b) {
    __nv_bfloat162 t = __floats2bfloat162_rn(a, b);
    return *(uint32_t*)&t;
}
__device__ __forceinline__ uint32_t s2u(const void* p) {
    uint32_t a;
    asm("{ .reg .u64 t; cvta.to.shared.u64 t, %1; cvt.u32.u64 %0, t; }" : "=r"(a) : "l"(p));
    return a;
}
__device__ __forceinline__ void cpa16(uint32_t d, const void* s) {
    asm volatile("cp.async.cg.shared.global [%0], [%1], 16;" :: "r"(d), "l"(s));
}
__device__ __forceinline__ void cpa4(uint32_t d, const void* s) {
    asm volatile("cp.async.ca.shared.global [%0], [%1], 4;" :: "r"(d), "l"(s));
}
#define CP_COMMIT() asm volatile("cp.async.commit_group;" ::: "memory")
#define CP_WAIT1()  asm volatile("cp.async.wait_group 1;" ::: "memory")
#define CP_WAIT0()  asm volatile("cp.async.wait_group 0;" ::: "memory")

// ---------------------------------------------------------------------------
// Kernel 0a/0b: fp32 -> bf16 conversions, merged launches (grid.y = tensor).
// ---------------------------------------------------------------------------
__device__ __forceinline__ void conv_one(const float4* src, __nv_bfloat16* hi,
                                         __nv_bfloat16* lo, int i, int do_split)
{
    float4 v = src[i];
    __nv_bfloat16 h0 = __float2bfloat16(v.x), h1 = __float2bfloat16(v.y);
    __nv_bfloat16 h2 = __float2bfloat16(v.z), h3 = __float2bfloat16(v.w);
    __nv_bfloat162* dh = (__nv_bfloat162*)hi;
    dh[2*i]   = __nv_bfloat162(h0, h1);
    dh[2*i+1] = __nv_bfloat162(h2, h3);
    if (do_split) {
        __nv_bfloat162* dl = (__nv_bfloat162*)lo;
        dl[2*i]   = __nv_bfloat162(__float2bfloat16(v.x - __bfloat162float(h0)),
                                   __float2bfloat16(v.y - __bfloat162float(h1)));
        dl[2*i+1] = __nv_bfloat162(__float2bfloat16(v.z - __bfloat162float(h2)),
                                   __float2bfloat16(v.w - __bfloat162float(h3)));
    }
}
__global__ void f2bf_x(const float4* __restrict__ q, const float4* __restrict__ k,
                       const float4* __restrict__ v)
{
    const int z = blockIdx.y;
    const float4* src = (z == 0) ? q : (z == 1) ? k : v;
    int i = blockIdx.x * blockDim.x + threadIdx.x;
    conv_one(src, g_xb + (size_t)z * 4096 * 1024, g_xb + (size_t)3 * 4096 * 1024, i, z == 2);
}
__global__ void f2bf_w(const float4* __restrict__ wq, const float4* __restrict__ wk,
                       const float4* __restrict__ wv)
{
    const int z = blockIdx.y;
    const float4* src = (z == 0) ? wq : (z == 1) ? wk : wv;
    int i = blockIdx.x * blockDim.x + threadIdx.x;
    conv_one(src, g_wb + (size_t)z * 1024 * 1024, g_wb + (size_t)3 * 1024 * 1024, i, z == 2);
}

// ---------------------------------------------------------------------------
// Kernel 1a: Q/K projections, 2-stage cp.async double-buffered, ldmatrix frags.
// ---------------------------------------------------------------------------
__global__ __launch_bounds__(256) void proj_qk(
    const float* __restrict__ bq, const float* __restrict__ bk)
{
    extern __shared__ __align__(16) char smraw[];

    const int z = blockIdx.z;
    const __nv_bfloat16* Xg = g_xb + (size_t)z * 4096 * 1024;
    const __nv_bfloat16* Wg = g_wb + (size_t)z * 1024 * 1024;
    const float* bias = z ? bk : bq;

    const int hp = blockIdx.x;
    const int m0 = blockIdx.y * 128;
    const int tid = threadIdx.x;
    const int wid = tid >> 5, lane = tid & 31;
    const int warpM = wid >> 1, warpN = wid & 1;
    const int gp = lane >> 2, tig = lane & 3;

    // ldmatrix lane-relative offsets (bytes)
    const int aRow = lane & 15, aK = lane >> 4;            // A operand
    const int mrow = (lane & 7) | ((lane >> 4) << 3);      // B operand
    const int ksub = (lane >> 3) & 1;
    uint32_t offA[2], offB[4];
    #pragma unroll
    for (int mi = 0; mi < 2; mi++)
        offA[mi] = ((warpM * 32 + mi * 16 + aRow) * PADW + aK * 8) * 2;
    #pragma unroll
    for (int g = 0; g < 4; g++)
        offB[g] = ((warpN * 64 + g * 16 + mrow) * PADW + ksub * 8) * 2;

    auto prefetch = [&](int c) {
        const int st = c & 1;
        __nv_bfloat16* Xh = (__nv_bfloat16*)(smraw + st * 2 * TILE_B);
        __nv_bfloat16* Wh = Xh + 128 * PADW;
        const int k0 = c * 64;
        #pragma unroll
        for (int j = 0; j < 4; j++) {
            int u = tid + j * 256;
            int r = u >> 3, cg = (u & 7) * 8;
            cpa16(s2u(&Xh[r * PADW + cg]), Xg + (size_t)(m0 + r) * NE + k0 + cg);
            cpa16(s2u(&Wh[r * PADW + cg]), Wg + (size_t)(hp * 128 + r) * NE + k0 + cg);
        }
    };

    prefetch(0); CP_COMMIT();

    float acc[2][8][4] = {};

    for (int c = 0; c < 16; c++) {
        if (c < 15) { prefetch(c + 1); CP_COMMIT(); CP_WAIT1(); }
        else        { CP_WAIT0(); }
        __syncthreads();

        const int st = c & 1;
        const uint32_t xaddr = s2u(smraw + st * 2 * TILE_B);
        const uint32_t waddr = xaddr + TILE_B;

        #pragma unroll
        for (int ks = 0; ks < 4; ks++) {
            uint32_t a[2][4], b[8][2];
            #pragma unroll
            for (int mi = 0; mi < 2; mi++)
                ldsm4(a[mi][0], a[mi][1], a[mi][2], a[mi][3], xaddr + offA[mi] + ks * 32);
            #pragma unroll
            for (int g = 0; g < 4; g++)
                ldsm4(b[g*2][0], b[g*2][1], b[g*2+1][0], b[g*2+1][1], waddr + offB[g] + ks * 32);
            #pragma unroll
            for (int ni = 0; ni < 8; ni++)
                #pragma unroll
                for (int mi = 0; mi < 2; mi++) mma16816(acc[mi][ni], a[mi], b[ni]);
        }
        __syncthreads();
    }

    const int b  = m0 >> 11;
    const int s0 = m0 & (NS - 1);
    const float sc = (z == 0) ? QSCALE : 1.0f;
    __nv_bfloat16* dst = (z == 0) ? g_qb : g_kb;
    const int head = hp * 2 + warpN;
    const size_t bh = (size_t)(b * NH + head);
    #pragma unroll
    for (int mi = 0; mi < 2; mi++)
        #pragma unroll
        for (int ni = 0; ni < 8; ni++) {
            const int r = warpM * 32 + mi * 16 + gp;
            const int d = ni * 8 + tig * 2;
            const float bx = bias[head * 64 + d], by = bias[head * 64 + d + 1];
            #pragma unroll
            for (int half = 0; half < 2; half++) {
                const int s = s0 + r + half * 8;
                float v0 = (acc[mi][ni][2*half+0] + bx) * sc;
                float v1 = (acc[mi][ni][2*half+1] + by) * sc;
                *(uint32_t*)&dst[(bh * NS + s) * ND + d] = pack_bf16x2(v0, v1);
            }
        }
}

// ---------------------------------------------------------------------------
// Kernel 1b: V projection (3-mma split-precision), 2-stage pipeline, ldmatrix.
// ---------------------------------------------------------------------------
__global__ __launch_bounds__(256) void proj_v(const float* __restrict__ bv)
{
    extern __shared__ __align__(16) char smraw[];

    const __nv_bfloat16* Xg  = g_xb + (size_t)2 * 4096 * 1024;
    const __nv_bfloat16* Wg  = g_wb + (size_t)2 * 1024 * 1024;
    const __nv_bfloat16* XgL = g_xb + (size_t)3 * 4096 * 1024;
    const __nv_bfloat16* WgL = g_wb + (size_t)3 * 1024 * 1024;

    const int hp = blockIdx.x;
    const int m0 = blockIdx.y * 128;
    const int tid = threadIdx.x;
    const int wid = tid >> 5, lane = tid & 31;
    const int warpM = wid >> 1, warpN = wid & 1;
    const int gp = lane >> 2, tig = lane & 3;

    const int aRow = lane & 15, aK = lane >> 4;
    const int mrow = (lane & 7) | ((lane >> 4) << 3);
    const int ksub = (lane >> 3) & 1;
    uint32_t offA[2], offB[4];
    #pragma unroll
    for (int mi = 0; mi < 2; mi++)
        offA[mi] = ((warpM * 32 + mi * 16 + aRow) * PADW + aK * 8) * 2;
    #pragma unroll
    for (int g = 0; g < 4; g++)
        offB[g] = ((warpN * 64 + g * 16 + mrow) * PADW + ksub * 8) * 2;

    auto prefetch = [&](int c) {
        const int st = c & 1;
        __nv_bfloat16* Xh = (__nv_bfloat16*)(smraw + st * 4 * TILE_B);
        __nv_bfloat16* Wh = Xh + 128 * PADW;
        __nv_bfloat16* Xl = Wh + 128 * PADW;
        __nv_bfloat16* Wl = Xl + 128 * PADW;
        const int k0 = c * 64;
        #pragma unroll
        for (int j = 0; j < 4; j++) {
            int u = tid + j * 256;
            int r = u >> 3, cg = (u & 7) * 8;
            cpa16(s2u(&Xh[r * PADW + cg]), Xg  + (size_t)(m0 + r) * NE + k0 + cg);
            cpa16(s2u(&Wh[r * PADW + cg]), Wg  + (size_t)(hp * 128 + r) * NE + k0 + cg);
            cpa16(s2u(&Xl[r * PADW + cg]), XgL + (size_t)(m0 + r) * NE + k0 + cg);
            cpa16(s2u(&Wl[r * PADW + cg]), WgL + (size_t)(hp * 128 + r) * NE + k0 + cg);
        }
    };

    prefetch(0); CP_COMMIT();

    float acc[2][8][4] = {};

    for (int c = 0; c < 16; c++) {
        if (c < 15) { prefetch(c + 1); CP_COMMIT(); CP_WAIT1(); }
        else        { CP_WAIT0(); }
        __syncthreads();

        const int st = c & 1;
        const uint32_t xaddr  = s2u(smraw + st * 4 * TILE_B);
        const uint32_t waddr  = xaddr + TILE_B;
        const uint32_t xladdr = xaddr + 2 * TILE_B;
        const uint32_t wladdr = xaddr + 3 * TILE_B;

        #pragma unroll
        for (int ks = 0; ks < 4; ks++) {
            uint32_t a[2][4], al[2][4], b[8][2], bl[8][2];
            #pragma unroll
            for (int mi = 0; mi < 2; mi++) {
                ldsm4(a[mi][0],  a[mi][1],  a[mi][2],  a[mi][3],  xaddr  + offA[mi] + ks * 32);
                ldsm4(al[mi][0], al[mi][1], al[mi][2], al[mi][3], xladdr + offA[mi] + ks * 32);
            }
            #pragma unroll
            for (int g = 0; g < 4; g++) {
                ldsm4(b[g*2][0],  b[g*2][1],  b[g*2+1][0],  b[g*2+1][1],  waddr  + offB[g] + ks * 32);
                ldsm4(bl[g*2][0], bl[g*2][1], bl[g*2+1][0], bl[g*2+1][1], wladdr + offB[g] + ks * 32);
            }
            #pragma unroll
            for (int ni = 0; ni < 8; ni++)
                #pragma unroll
                for (int mi = 0; mi < 2; mi++) {
                    mma16816(acc[mi][ni], a[mi],  b[ni]);
                    mma16816(acc[mi][ni], a[mi],  bl[ni]);
                    mma16816(acc[mi][ni], al[mi], b[ni]);
                }
        }
        __syncthreads();
    }

    const int b  = m0 >> 11;
    const int s0 = m0 & (NS - 1);

    float* Vst = (float*)smraw;    // [128][131] staging
    #pragma unroll
    for (int mi = 0; mi < 2; mi++)
        #pragma unroll
        for (int ni = 0; ni < 8; ni++) {
            const int r = warpM * 32 + mi * 16 + gp;
            const int cn = warpN * 64 + ni * 8 + tig * 2;
            const float bx = bv[hp * 128 + cn], by = bv[hp * 128 + cn + 1];
            #pragma unroll
            for (int half = 0; half < 2; half++) {
                const int rr = r + half * 8;
                Vst[rr * 131 + cn    ] = acc[mi][ni][2*half+0] + bx;
                Vst[rr * 131 + cn + 1] = acc[mi][ni][2*half+1] + by;
            }
        }
    __syncthreads();
    #pragma unroll
    for (int i = 0; i < 16; i++) {
        int u = tid + i * 256;
        int r = u >> 5, c4 = (u & 31) * 4;
        int head = hp * 2 + (c4 >> 6), d = c4 & 63;
        float4 w = make_float4(Vst[r*131+c4], Vst[r*131+c4+1], Vst[r*131+c4+2], Vst[r*131+c4+3]);
        *(float4*)&g_v[((size_t)(b * NH + head) * NS + s0 + r) * ND + d] = w;
    }
    const int t0 = s0 >> 6;
    #pragma unroll
    for (int i = 0; i < 32; i++) {
        int u = tid + i * 256;
        int j = (u & 31) * 2, cc = (u >> 5) & 127, tl = u >> 12;
        int head = hp * 2 + (cc >> 6), d = cc & 63;
        uint32_t p = pack_bf16x2(Vst[(tl*64 + j)*131 + cc], Vst[(tl*64 + j + 1)*131 + cc]);
        *(uint32_t*)&g_vtb[(((size_t)(b * NH + head) * NT + t0 + tl) * ND + d) * 64 + j] = p;
    }
}

// ---------------------------------------------------------------------------
// Kernels 2a/2b/2c: parallel per-row exclusive suffix sums (register-buffered).
// ---------------------------------------------------------------------------
__global__ void tile_sum_kernel()
{
    const int bh = blockIdx.x, t = blockIdx.y, d = threadIdx.x;
    const float* v = g_v + ((size_t)bh * NS + t * 64) * ND + d;
    float vals[64];
    #pragma unroll
    for (int j = 0; j < 64; j++) vals[j] = v[(size_t)j * ND];
    float a = 0.f;
    #pragma unroll
    for (int j = 0; j < 64; j++) a += vals[j];
    g_tsum[((size_t)bh * NT + t) * ND + d] = a;
}
__global__ void tile_suffix_kernel()
{
    const int bh = blockIdx.x, d = threadIdx.x;
    float vals[NT];
    #pragma unroll
    for (int t = 0; t < NT; t++) vals[t] = g_tsum[((size_t)bh * NT + t) * ND + d];
    float acc = 0.f;
    #pragma unroll
    for (int t = NT - 1; t >= 0; t--) {
        g_tsuf[((size_t)bh * NT + t) * ND + d] = acc;
        acc += vals[t];
    }
    g_vt[bh * ND + d] = acc;
}
__global__ void row_suffix_kernel()
{
    const int bh = blockIdx.x, t = blockIdx.y, d = threadIdx.x;
    const float* v = g_v + ((size_t)bh * NS + t * 64) * ND + d;
    float vals[64];
    #pragma unroll
    for (int j = 0; j < 64; j++) vals[j] = v[(size_t)j * ND];
    float acc = g_tsuf[((size_t)bh * NT + t) * ND + d];
    float* sx = g_sufx + ((size_t)bh * NS + t * 64) * ND + d;
    #pragma unroll
    for (int j = 63; j >= 0; j--) {
        sx[(size_t)j * ND] = acc;
        acc += vals[j];
    }
}

// ---------------------------------------------------------------------------
// Kernel 3: register-resident flash attention; 4-slot cp.async pipeline,
// pair-processed mainloop, ldmatrix fragment loads.  (R15 structure.)
// ---------------------------------------------------------------------------
__global__ __launch_bounds__(256, 2) void attn_mma(
    const float* __restrict__ pos_bias, float* __restrict__ out)
{
    extern __shared__ __align__(16) char smr[];
    __nv_bfloat16* Qb  = (__nv_bfloat16*)smr;        // [64][72]
    __nv_bfloat16* KV0 = Qb + 64 * PADW;             // 4 slots x (K,V), each 64*PADW
    float* posw  = (float*)(KV0 + 8 * KVBUF);        // [4][128]
    float* pm    = posw + 512;                       // [64][2]
    float* pl    = pm + 128;                         // [64][2]
    float* lse_s = pl + 128;                         // [64]
    float* Obuf  = (float*)smr;                      // overlay [64][66]

    const int tq = NT - 1 - blockIdx.x;              // heavy blocks first
    const int h  = blockIdx.y;
    const int b  = blockIdx.z;
    const int bh = b * NH + h;
    const int q0 = tq * 64;
    const int tid = threadIdx.x;
    const int wid = tid >> 5, lane = tid & 31;
    const int warpM = wid >> 1, warpN = wid & 1;
    const int gp = lane >> 2, tig = lane & 3;
    const int rbase = warpM * 16 + gp;

    const int mrow = (lane & 7) | ((lane >> 4) << 3);
    const int ksub = (lane >> 3) & 1;
    uint32_t qk_off[2], sv_off[4];
    #pragma unroll
    for (int g = 0; g < 2; g++)
        qk_off[g] = ((warpN * 32 + g * 16 + mrow) * PADW + ksub * 8) * 2;
    #pragma unroll
    for (int g2 = 0; g2 < 4; g2++)
        sv_off[g2] = ((g2 * 16 + mrow) * PADW + warpN * 32 + ksub * 8) * 2;

    auto prefetch = [&](int t) {
        const int s = t & 3;
        const int k0 = t * 64;
        __nv_bfloat16* Ks = KV0 + s * 2 * KVBUF;
        __nv_bfloat16* Vs = Ks + KVBUF;
        #pragma unroll
        for (int j = 0; j < 2; j++) {
            int u = tid + j * 256;
            int r = u >> 3, cg = (u & 7) * 8;
            cpa16(s2u(&Ks[r * PADW + cg]), g_kb + ((size_t)bh * NS + k0 + r) * ND + cg);
            cpa16(s2u(&Vs[r * PADW + cg]), g_vtb + (((size_t)bh * NT + t) * ND + r) * 64 + cg);
        }
        if (tid < 128) {
            int idx = q0 - k0 - 63 + tid + NS - 1;
            if (idx <= 2 * NS - 2)
                cpa4(s2u(&posw[s * 128 + tid]), &pos_bias[(size_t)h * (2 * NS - 1) + idx]);
            else
                posw[s * 128 + tid] = 0.f;
        }
    };

    prefetch(0);
    if (tq >= 1) prefetch(1);
    CP_COMMIT();
    if (tq >= 2) prefetch(2);
    if (tq >= 3) prefetch(3);
    CP_COMMIT();

    #pragma unroll
    for (int j = 0; j < 2; j++) {
        int u = tid + j * 256;
        int r = u >> 3, cg = (u & 7) * 8;
        *(uint4*)&Qb[r * PADW + cg] = *(const uint4*)(g_qb + ((size_t)bh * NS + q0 + r) * ND + cg);
    }
    __syncthreads();
    uint32_t aq[4][4];
    #pragma unroll
    for (int ks = 0; ks < 4; ks++) {
        const int kc = ks * 16 + tig * 2;
        aq[ks][0] = *(const uint32_t*)&Qb[(rbase    ) * PADW + kc];
        aq[ks][1] = *(const uint32_t*)&Qb[(rbase + 8) * PADW + kc];
        aq[ks][2] = *(const uint32_t*)&Qb[(rbase    ) * PADW + kc + 8];
        aq[ks][3] = *(const uint32_t*)&Qb[(rbase + 8) * PADW + kc + 8];
    }

    float oacc[8][4] = {};
    float m0r = NEGM, l0r = 0.f, m1r = NEGM, l1r = 0.f;

    auto compute_tile = [&](int t) {
        const bool diag = (t == tq);
        const int s = t & 3;
        const __nv_bfloat16* Ks = KV0 + s * 2 * KVBUF;
        const float* pw = posw + s * 128;
        const uint32_t ksaddr = s2u(Ks);
        const uint32_t vsaddr = ksaddr + KVBUF * 2;

        float cS[4][4] = {};
        #pragma unroll
        for (int ks = 0; ks < 4; ks++) {
            uint32_t bb[4][2];
            #pragma unroll
            for (int g = 0; g < 2; g++)
                ldsm4(bb[g*2][0], bb[g*2][1], bb[g*2+1][0], bb[g*2+1][1],
                      ksaddr + qk_off[g] + ks * 32);
            #pragma unroll
            for (int ni = 0; ni < 4; ni++) mma16816(cS[ni], aq[ks], bb[ni]);
        }

        float e0[8], e1[8];
        uint32_t sf[2][4];
        #pragma unroll
        for (int ni = 0; ni < 4; ni++) {
            const int kcol = warpN * 32 + ni * 8 + tig * 2;
            float v00 = cS[ni][0] + pw[rbase     - kcol + 63];
            float v01 = cS[ni][1] + pw[rbase     - kcol + 62];
            float v10 = cS[ni][2] + pw[rbase + 8 - kcol + 63];
            float v11 = cS[ni][3] + pw[rbase + 8 - kcol + 62];
            float p00 = v00, p01 = v01, p10 = v10, p11 = v11;
            if (diag) {
                if (kcol     > rbase)     { v00 = NEGM; p00 = 0.f; }
                if (kcol + 1 > rbase)     { v01 = NEGM; p01 = 0.f; }
                if (kcol     > rbase + 8) { v10 = NEGM; p10 = 0.f; }
                if (kcol + 1 > rbase + 8) { v11 = NEGM; p11 = 0.f; }
            }
            e0[ni*2] = v00; e0[ni*2+1] = v01;
            e1[ni*2] = v10; e1[ni*2+1] = v11;
            const int ks2 = ni >> 1;
            if ((ni & 1) == 0) {
                sf[ks2][0] = pack_bf16x2(p00, p01);
                sf[ks2][1] = pack_bf16x2(p10, p11);
            } else {
                sf[ks2][2] = pack_bf16x2(p00, p01);
                sf[ks2][3] = pack_bf16x2(p10, p11);
            }
        }
        {
            float vm = e0[0];
            #pragma unroll
            for (int j = 1; j < 8; j++) vm = fmaxf(vm, e0[j]);
            float mn = fmaxf(m0r, vm);
            float sum = 0.f;
            #pragma unroll
            for (int j = 0; j < 8; j++) sum += __expf(e0[j] - mn);
            l0r = l0r * __expf(m0r - mn) + sum; m0r = mn;
        }
        {
            float vm = e1[0];
            #pragma unroll
            for (int j = 1; j < 8; j++) vm = fmaxf(vm, e1[j]);
            float mn = fmaxf(m1r, vm);
            float sum = 0.f;
            #pragma unroll
            for (int j = 0; j < 8; j++) sum += __expf(e1[j] - mn);
            l1r = l1r * __expf(m1r - mn) + sum; m1r = mn;
        }

        #pragma unroll
        for (int ks2 = 0; ks2 < 2; ks2++) {
            #pragma unroll
            for (int g2 = 0; g2 < 4; g2++) {
                uint32_t t0r, t1r, t2r, t3r;
                ldsm4(t0r, t1r, t2r, t3r, vsaddr + sv_off[g2] + ks2 * 32);
                uint32_t ba[2] = {t0r, t1r}, bc[2] = {t2r, t3r};
                mma16816(oacc[g2*2    ], sf[ks2], ba);
                mma16816(oacc[g2*2 + 1], sf[ks2], bc);
            }
        }
    };

    for (int t0 = 0; t0 <= tq; t0 += 2) {
        CP_WAIT1();
        __syncthreads();
        compute_tile(t0);
        if (t0 + 1 <= tq) compute_tile(t0 + 1);
        __syncthreads();
        if (t0 + 4 <= tq) prefetch(t0 + 4);
        if (t0 + 5 <= tq) prefetch(t0 + 5);
        CP_COMMIT();
    }

    CP_WAIT0();
    __syncthreads();
    #pragma unroll
    for (int d = 1; d < 4; d <<= 1) {
        float mo = __shfl_xor_sync(0xffffffffu, m0r, d);
        float lo = __shfl_xor_sync(0xffffffffu, l0r, d);
        float mn = fmaxf(m0r, mo);
        l0r = l0r * __expf(m0r - mn) + lo * __expf(mo - mn); m0r = mn;
        mo = __shfl_xor_sync(0xffffffffu, m1r, d);
        lo = __shfl_xor_sync(0xffffffffu, l1r, d);
        mn = fmaxf(m1r, mo);
        l1r = l1r * __expf(m1r - mn) + lo * __expf(mo - mn); m1r = mn;
    }
    if (tig == 0) {
        pm[rbase * 2 + warpN] = m0r;       pl[rbase * 2 + warpN] = l0r;
        pm[(rbase + 8) * 2 + warpN] = m1r; pl[(rbase + 8) * 2 + warpN] = l1r;
    }
    __syncthreads();
    if (tid < 64) {
        float ma = pm[tid*2], mb_ = pm[tid*2+1], la = pl[tid*2], lb = pl[tid*2+1];
        float mn = fmaxf(ma, mb_);
        lse_s[tid] = mn + logf(la * __expf(ma - mn) + lb * __expf(mb_ - mn));
    }
    __syncthreads();
    if (warpN == 1) {
        #pragma unroll
        for (int ni = 0; ni < 8; ni++) {
            const int d = ni * 8 + tig * 2;
            Obuf[rbase * 66 + d]           = oacc[ni][0];
            Obuf[rbase * 66 + d + 1]       = oacc[ni][1];
            Obuf[(rbase + 8) * 66 + d]     = oacc[ni][2];
            Obuf[(rbase + 8) * 66 + d + 1] = oacc[ni][3];
        }
    }
    __syncthreads();
    if (warpN == 0) {
        const float lse0 = lse_s[rbase], lse1 = lse_s[rbase + 8];
        const int q0r = q0 + rbase;
        #pragma unroll
        for (int ni = 0; ni < 8; ni++) {
            const int d = ni * 8 + tig * 2;
            float2 vt2 = *(const float2*)&g_vt[bh * ND + d];
            float2 sx0 = *(const float2*)&g_sufx[((size_t)bh * NS + q0r    ) * ND + d];
            float2 sx1 = *(const float2*)&g_sufx[((size_t)bh * NS + q0r + 8) * ND + d];
            float2 o0, o1;
            o0.x = oacc[ni][0] + Obuf[rbase * 66 + d]     + NEGV * sx0.x - lse0 * vt2.x;
            o0.y = oacc[ni][1] + Obuf[rbase * 66 + d + 1] + NEGV * sx0.y - lse0 * vt2.y;
            o1.x = oacc[ni][2] + Obuf[(rbase+8) * 66 + d]     + NEGV * sx1.x - lse1 * vt2.x;
            o1.y = oacc[ni][3] + Obuf[(rbase+8) * 66 + d + 1] + NEGV * sx1.y - lse1 * vt2.y;
            *(float2*)&out[(((size_t)b * NS + q0r    ) * NH + h) * ND + d] = o0;
            *(float2*)&out[(((size_t)b * NS + q0r + 8) * NH + h) * ND + d] = o1;
        }
    }
}

// ---------------------------------------------------------------------------
extern "C" void kernel_launch(void* const* d_in, const int* in_sizes, int n_in,
                              void* d_out, int out_size)
{
    (void)in_sizes; (void)n_in; (void)out_size;
    const float* query = (const float*)d_in[0];
    const float* key_  = (const float*)d_in[1];
    const float* value = (const float*)d_in[2];
    const float* Wq    = (const float*)d_in[3];
    const float* bq    = (const float*)d_in[4];
    const float* Wk    = (const float*)d_in[5];
    const float* bk    = (const float*)d_in[6];
    const float* Wv    = (const float*)d_in[7];
    const float* bv    = (const float*)d_in[8];
    const float* pos   = (const float*)d_in[9];

    f2bf_x<<<dim3(4096, 3), 256>>>((const float4*)query, (const float4*)key_, (const float4*)value);
    f2bf_w<<<dim3(1024, 3), 256>>>((const float4*)Wq, (const float4*)Wk, (const float4*)Wv);

    const int QK_SMEM = 2 * 2 * TILE_B;                 // 73728 B
    const int V_SMEM  = 2 * 4 * TILE_B;                 // 147456 B
    cudaFuncSetAttribute(proj_qk, cudaFuncAttributeMaxDynamicSharedMemorySize, QK_SMEM);
    cudaFuncSetAttribute(proj_v,  cudaFuncAttributeMaxDynamicSharedMemorySize, V_SMEM);
    proj_qk<<<dim3(8, 32, 2), 256, QK_SMEM>>>(bq, bk);
    proj_v<<<dim3(8, 32), 256, V_SMEM>>>(bv);

    tile_sum_kernel<<<dim3(NB * NH, NT), 64>>>();
    tile_suffix_kernel<<<dim3(NB * NH), 64>>>();
    row_suffix_kernel<<<dim3(NB * NH, NT), 64>>>();

    // Qb + 4*(K,V) + posw[4][128] + pm/pl/lse
    const int ATTN_SMEM = 64*PADW*2 + 8*KVBUF*2 + (512 + 128 + 128 + 64) * 4;  // 86272 B
    cudaFuncSetAttribute(attn_mma, cudaFuncAttributeMaxDynamicSharedMemorySize, ATTN_SMEM);
    attn_mma<<<dim3(NT, NH, NB), 256, ATTN_SMEM>>>(pos, (float*)d_out);
}